// round 7
// baseline (speedup 1.0000x reference)
#include <cuda_runtime.h>

#define NV 5
#define NS 4
#define CC 32
#define HH 128
#define WW 160
#define DDEP 48
#define HWSZ (HH*WW)          // 20480
#define DHWSZ (DDEP*HWSZ)     // 983040

// conv tiling
#define HT 4
#define HS 6
#define DT 8
#define DS 10
#define WP 168
#define CONV_THREADS 160
#define CSPLIT 4
#define CPB (CC/CSPLIT)       // 8 channels per block

// ---------------- scratch ----------------------------------------------------
__device__ float g_rot[NS][9];
__device__ float g_trans[NS][3];
__device__ float g_feaT[NV*HWSZ*CC];            // (view, h, w, c)
__device__ float g_var[(size_t)CC*DHWSZ];       // planar (c, d,h,w)
__device__ float g_costp[CSPLIT][DHWSZ];        // partial costs

// ---------------- packed f32x2 helpers --------------------------------------
__device__ __forceinline__ unsigned long long pk2(float lo, float hi) {
    unsigned long long p;
    asm("mov.b64 %0, {%1, %2};" : "=l"(p) : "f"(lo), "f"(hi));
    return p;
}
__device__ __forceinline__ unsigned long long fma2(unsigned long long a,
                                                   unsigned long long b,
                                                   unsigned long long c) {
    unsigned long long d;
    asm("fma.rn.f32x2 %0, %1, %2, %3;" : "=l"(d) : "l"(a), "l"(b), "l"(c));
    return d;
}
__device__ __forceinline__ unsigned long long mul2(unsigned long long a,
                                                   unsigned long long b) {
    unsigned long long d;
    asm("mul.rn.f32x2 %0, %1, %2;" : "=l"(d) : "l"(a), "l"(b));
    return d;
}
__device__ __forceinline__ unsigned long long add2(unsigned long long a,
                                                   unsigned long long b) {
    unsigned long long d;
    asm("add.rn.f32x2 %0, %1, %2;" : "=l"(d) : "l"(a), "l"(b));
    return d;
}
__device__ __forceinline__ void upk2(unsigned long long p, float& lo, float& hi) {
    asm("mov.b64 {%0, %1}, %2;" : "=f"(lo), "=f"(hi) : "l"(p));
}

// ---------------- kernel 0: projection setup (1 thread, fp32) ---------------
__global__ void k_setup(const float* __restrict__ pm) {
    if (threadIdx.x != 0 || blockIdx.x != 0) return;
    float fused[NV][16];
    for (int n = 0; n < NV; n++) {
        const float* p0 = pm + n * 32;
        const float* p1 = p0 + 16;
        for (int i = 0; i < 16; i++) fused[n][i] = p0[i];
        for (int i = 0; i < 3; i++)
            for (int j = 0; j < 4; j++) {
                float s = 0.0f;
                for (int k = 0; k < 3; k++) s += p1[i*4+k] * p0[k*4+j];
                fused[n][i*4+j] = s;
            }
    }
    float a[4][8];
    for (int i = 0; i < 4; i++)
        for (int j = 0; j < 4; j++) {
            a[i][j]   = fused[0][i*4+j];
            a[i][j+4] = (i == j) ? 1.0f : 0.0f;
        }
    for (int col = 0; col < 4; col++) {
        int piv = col;
        for (int r = col + 1; r < 4; r++)
            if (fabsf(a[r][col]) > fabsf(a[piv][col])) piv = r;
        if (piv != col)
            for (int j = 0; j < 8; j++) { float t = a[col][j]; a[col][j] = a[piv][j]; a[piv][j] = t; }
        float d = a[col][col];
        for (int j = 0; j < 8; j++) a[col][j] /= d;
        for (int r = 0; r < 4; r++) {
            if (r == col) continue;
            float f = a[r][col];
            for (int j = 0; j < 8; j++) a[r][j] -= f * a[col][j];
        }
    }
    float inv[16];
    for (int i = 0; i < 4; i++)
        for (int j = 0; j < 4; j++) inv[i*4+j] = a[i][j+4];

    for (int v = 1; v < NV; v++) {
        float P[16];
        for (int i = 0; i < 4; i++)
            for (int j = 0; j < 4; j++) {
                float s = 0.0f;
                for (int k = 0; k < 4; k++) s += fused[v][i*4+k] * inv[k*4+j];
                P[i*4+j] = s;
            }
        for (int i = 0; i < 3; i++)
            for (int j = 0; j < 3; j++) g_rot[v-1][i*3+j] = P[i*4+j];
        for (int i = 0; i < 3; i++) g_trans[v-1][i] = P[i*4+3];
    }
}

// ---------------- kernel 1: transpose features (N,C,H,W) -> (N,HW,C) --------
__global__ void k_transpose(const float* __restrict__ f) {
    __shared__ float tile[32][33];
    int n  = blockIdx.z;
    int p0 = blockIdx.x * 32;
    int tx = threadIdx.x, ty = threadIdx.y;
    tile[ty][tx] = f[((size_t)(n*CC + ty))*HWSZ + p0 + tx];
    __syncthreads();
    g_feaT[((size_t)(n*HWSZ + p0 + ty))*CC + tx] = tile[tx][ty];
}

// ---------------- kernel 2: warp + variance, f32x2 gather math --------------
__global__ void __launch_bounds__(128) k_var(const float* __restrict__ dv) {
    __shared__ int4   s_idx[4][4][32];
    __shared__ float4 s_wt [4][4][32];
    __shared__ int    s_hw [4][32];
    __shared__ float  s_var[128*33];

    const int tid  = threadIdx.x;
    const int warp = tid >> 5;
    const int lane = tid & 31;
    const int gblock = blockIdx.x * 128;

    {
        int g  = gblock + tid;
        int d  = g / HWSZ;
        int hw = g - d * HWSZ;
        int h  = hw / WW;
        int w  = hw - h * WW;
        float fx = (float)w, fy = (float)h;
        float depth = __ldg(dv + d);
        #pragma unroll
        for (int v = 0; v < NS; v++) {
            float r0 = g_rot[v][0], r1 = g_rot[v][1], r2 = g_rot[v][2];
            float r3 = g_rot[v][3], r4 = g_rot[v][4], r5 = g_rot[v][5];
            float r6 = g_rot[v][6], r7 = g_rot[v][7], r8 = g_rot[v][8];
            float t0 = g_trans[v][0], t1 = g_trans[v][1], t2 = g_trans[v][2];
            float rx = r0*fx + r1*fy + r2;
            float ry = r3*fx + r4*fy + r5;
            float rz = r6*fx + r7*fy + r8;
            float X = rx*depth + t0;
            float Y = ry*depth + t1;
            float Z = rz*depth + t2;
            float px = X / Z;
            float py = Y / Z;
            float x0 = floorf(px), y0 = floorf(py);
            float x1 = x0 + 1.0f,  y1 = y0 + 1.0f;
            float wx1 = px - x0, wx0 = 1.0f - wx1;
            float wy1 = py - y0, wy0 = 1.0f - wy1;
            bool vx0 = (x0 >= 0.0f) && (x0 <= (float)(WW-1));
            bool vx1 = (x1 >= 0.0f) && (x1 <= (float)(WW-1));
            bool vy0 = (y0 >= 0.0f) && (y0 <= (float)(HH-1));
            bool vy1 = (y1 >= 0.0f) && (y1 <= (float)(HH-1));
            int cx0 = (int)fminf(fmaxf(x0, 0.0f), (float)(WW-1));
            int cx1 = (int)fminf(fmaxf(x1, 0.0f), (float)(WW-1));
            int cy0 = (int)fminf(fmaxf(y0, 0.0f), (float)(HH-1));
            int cy1 = (int)fminf(fmaxf(y1, 0.0f), (float)(HH-1));
            int4 id;
            id.x = cy0*WW + cx0;
            id.y = cy0*WW + cx1;
            id.z = cy1*WW + cx0;
            id.w = cy1*WW + cx1;
            float4 wt;
            wt.x = wx0*wy0 * ((vx0 && vy0) ? 1.0f : 0.0f);
            wt.y = wx1*wy0 * ((vx1 && vy0) ? 1.0f : 0.0f);
            wt.z = wx0*wy1 * ((vx0 && vy1) ? 1.0f : 0.0f);
            wt.w = wx1*wy1 * ((vx1 && vy1) ? 1.0f : 0.0f);
            s_idx[warp][v][lane] = id;
            s_wt [warp][v][lane] = wt;
        }
        s_hw[warp][lane] = hw;
    }
    __syncwarp();

    const int cg = lane & 7;
    const int q  = lane >> 3;
    const ulonglong2* fT = (const ulonglong2*)g_feaT;   // 16B = 2 x f32x2
    const float invN = 1.0f / (float)NV;

    #pragma unroll
    for (int it = 0; it < 8; it++) {
        int pt  = it*4 + q;
        int hw2 = s_hw[warp][pt];
        ulonglong2 ref = fT[(size_t)hw2*8 + cg];
        unsigned long long s0 = ref.x, s1 = ref.y;                 // sum (ch pairs)
        unsigned long long q0 = mul2(ref.x, ref.x);                // sumsq
        unsigned long long q1 = mul2(ref.y, ref.y);
        #pragma unroll
        for (int v = 0; v < NS; v++) {
            int4   id = s_idx[warp][v][pt];
            float4 wt = s_wt [warp][v][pt];
            const ulonglong2* fv = fT + (size_t)(v+1)*HWSZ*8;
            ulonglong2 c00 = fv[(size_t)id.x*8 + cg];
            ulonglong2 c01 = fv[(size_t)id.y*8 + cg];
            ulonglong2 c10 = fv[(size_t)id.z*8 + cg];
            ulonglong2 c11 = fv[(size_t)id.w*8 + cg];
            unsigned long long w0 = pk2(wt.x, wt.x);
            unsigned long long w1 = pk2(wt.y, wt.y);
            unsigned long long w2 = pk2(wt.z, wt.z);
            unsigned long long w3 = pk2(wt.w, wt.w);
            unsigned long long v0 = fma2(c00.x, w0,
                                    fma2(c01.x, w1,
                                    fma2(c10.x, w2, mul2(c11.x, w3))));
            unsigned long long v1 = fma2(c00.y, w0,
                                    fma2(c01.y, w1,
                                    fma2(c10.y, w2, mul2(c11.y, w3))));
            s0 = add2(s0, v0);
            s1 = add2(s1, v1);
            q0 = fma2(v0, v0, q0);
            q1 = fma2(v1, v1, q1);
        }
        float sx, sy, sz, sw, qx, qy, qz, qw;
        upk2(s0, sx, sy); upk2(s1, sz, sw);
        upk2(q0, qx, qy); upk2(q1, qz, qw);
        float mx = sx*invN, my = sy*invN, mz = sz*invN, mw = sw*invN;
        float vrx = qx*invN - mx*mx;
        float vry = qy*invN - my*my;
        float vrz = qz*invN - mz*mz;
        float vrw = qw*invN - mw*mw;
        int sbase = (warp*32 + pt)*33 + cg*4;
        s_var[sbase+0] = vrx;
        s_var[sbase+1] = vry;
        s_var[sbase+2] = vrz;
        s_var[sbase+3] = vrw;
    }
    __syncthreads();

    int gg = gblock + tid;
    #pragma unroll
    for (int c = 0; c < CC; c++)
        g_var[(size_t)c*DHWSZ + gg] = s_var[tid*33 + c];
}

// ---------------- kernel 3: 3x3x3 conv, 8 channels per block (4-way split) --
__global__ void __launch_bounds__(CONV_THREADS, 4) k_conv(const float* __restrict__ wgt) {
    __shared__ float slab[HS][DS][WP];
    __shared__ unsigned long long wpk[CPB*27];

    const int tid = threadIdx.x;
    const int h0  = blockIdx.x * HT;
    const int d0  = blockIdx.y * DT;
    const int c0  = blockIdx.z * CPB;
    float* __restrict__ outbuf = g_costp[blockIdx.z];
    const int wg  = tid % 40;
    const int hl  = tid / 40;
    const int w0  = wg * 4;

    for (int i = tid; i < CPB*27; i += CONV_THREADS) {
        float k = __ldg(wgt + c0*27 + i);
        wpk[i] = pk2(k, k);
    }
    for (int i = tid; i < HS*DS; i += CONV_THREADS) {
        int shy = i / DS, sdd = i % DS;
        float* row = &slab[shy][sdd][0];
        row[0] = 0.f; row[1] = 0.f; row[2] = 0.f; row[3] = 0.f;
        row[164] = 0.f; row[165] = 0.f; row[166] = 0.f; row[167] = 0.f;
    }

    unsigned long long A[DT][2];
    #pragma unroll
    for (int od = 0; od < DT; od++) { A[od][0] = 0ull; A[od][1] = 0ull; }

    #pragma unroll 1
    for (int c = 0; c < CPB; c++) {
        __syncthreads();

        const float* __restrict__ vc = g_var + (size_t)(c0 + c) * DHWSZ;
        #pragma unroll
        for (int r = 0; r < 15; r++) {
            int idx = r*CONV_THREADS + tid;
            int row = idx / 40;
            int w4  = (idx % 40) * 4;
            int shy = row / DS;
            int sdd = row - shy*DS;
            int dd  = d0 - 1 + sdd;
            int hy  = h0 - 1 + shy;
            float4 v = make_float4(0.f, 0.f, 0.f, 0.f);
            if (dd >= 0 && dd < DDEP && hy >= 0 && hy < HH)
                v = *(const float4*)(vc + (size_t)dd*HWSZ + hy*WW + w4);
            *(float4*)&slab[shy][sdd][w4 + 4] = v;
        }
        __syncthreads();

        const unsigned long long* wc = wpk + c*27;
        #pragma unroll
        for (int dy = 0; dy < 3; dy++) {
            unsigned long long k00 = wc[(0*3+dy)*3+0], k01 = wc[(0*3+dy)*3+1], k02 = wc[(0*3+dy)*3+2];
            unsigned long long k10 = wc[(1*3+dy)*3+0], k11 = wc[(1*3+dy)*3+1], k12 = wc[(1*3+dy)*3+2];
            unsigned long long k20 = wc[(2*3+dy)*3+0], k21 = wc[(2*3+dy)*3+1], k22 = wc[(2*3+dy)*3+2];
            const float* hrow = &slab[hl + dy][0][0];
            #pragma unroll
            for (int sdd = 0; sdd < DS; sdd++) {
                const float* col = hrow + sdd*WP;
                float4 a = *(const float4*)(col + w0 + 4);
                float2 l = *(const float2*)(col + w0 + 2);
                float2 rr = *(const float2*)(col + w0 + 8);
                unsigned long long P0 = pk2(l.y,  a.x);
                unsigned long long P1 = pk2(a.x,  a.y);
                unsigned long long P2 = pk2(a.y,  a.z);
                unsigned long long P3 = pk2(a.z,  a.w);
                unsigned long long P4 = pk2(a.w,  rr.x);
                #pragma unroll
                for (int dz = 0; dz < 3; dz++) {
                    int od = sdd - dz;
                    if (od < 0 || od >= DT) continue;
                    unsigned long long q0 = (dz==0) ? k00 : (dz==1) ? k10 : k20;
                    unsigned long long q1 = (dz==0) ? k01 : (dz==1) ? k11 : k21;
                    unsigned long long q2 = (dz==0) ? k02 : (dz==1) ? k12 : k22;
                    A[od][0] = fma2(P0, q0, A[od][0]);
                    A[od][0] = fma2(P1, q1, A[od][0]);
                    A[od][0] = fma2(P2, q2, A[od][0]);
                    A[od][1] = fma2(P2, q0, A[od][1]);
                    A[od][1] = fma2(P3, q1, A[od][1]);
                    A[od][1] = fma2(P4, q2, A[od][1]);
                }
            }
        }
    }

    const int ob = (h0 + hl)*WW + w0;
    #pragma unroll
    for (int od = 0; od < DT; od++) {
        float o0, o1, o2, o3;
        upk2(A[od][0], o0, o1);
        upk2(A[od][1], o2, o3);
        float4 v = make_float4(o0, o1, o2, o3);
        *(float4*)(outbuf + (size_t)(d0 + od)*HWSZ + ob) = v;
    }
}

// ---------------- kernel 4: softmax / depth / confidence --------------------
__global__ void __launch_bounds__(128) k_post(const float* __restrict__ dv,
                                              float* __restrict__ out) {
    int pix = blockIdx.x * 128 + threadIdx.x;
    float p[DDEP];
    float mx = -1e30f;
    #pragma unroll
    for (int d = 0; d < DDEP; d++) {
        size_t o = (size_t)d*HWSZ + pix;
        p[d] = (g_costp[0][o] + g_costp[1][o]) + (g_costp[2][o] + g_costp[3][o]);
        mx = fmaxf(mx, p[d]);
    }
    float s = 0.0f;
    #pragma unroll
    for (int d = 0; d < DDEP; d++) { p[d] = expf(p[d] - mx); s += p[d]; }
    float inv = 1.0f / s;
    float depth = 0.0f, didx = 0.0f;
    #pragma unroll
    for (int d = 0; d < DDEP; d++) {
        float pr = p[d] * inv;
        p[d] = pr;
        depth += pr * __ldg(dv + d);
        didx  += pr * (float)d;
    }
    int di = (int)didx;
    di = min(max(di, 0), DDEP - 1);
    float conf = 0.0f;
    #pragma unroll
    for (int d = 0; d < DDEP; d++) {
        bool inwin = (d >= di - 1) && (d <= di + 2);
        conf += inwin ? p[d] : 0.0f;
    }
    out[pix]        = depth;
    out[HWSZ + pix] = conf;
}

// ---------------- launcher ---------------------------------------------------
extern "C" void kernel_launch(void* const* d_in, const int* in_sizes, int n_in,
                              void* d_out, int out_size) {
    const float* features = nullptr;
    const float* pm       = nullptr;
    const float* dv       = nullptr;
    const float* wgt      = nullptr;
    for (int i = 0; i < n_in; i++) {
        switch (in_sizes[i]) {
            case NV*CC*HWSZ: features = (const float*)d_in[i]; break;
            case 160:        pm       = (const float*)d_in[i]; break;
            case 48:         dv       = (const float*)d_in[i]; break;
            case 864:        wgt      = (const float*)d_in[i]; break;
            default: break;
        }
    }
    if (!features) features = (const float*)d_in[0];
    if (!pm)       pm       = (const float*)d_in[1];
    if (!dv)       dv       = (const float*)d_in[2];
    if (!wgt)      wgt      = (const float*)d_in[3];
    float* out = (float*)d_out;

    k_setup<<<1, 32>>>(pm);
    k_transpose<<<dim3(HWSZ/32, 1, NV), dim3(32, 32)>>>(features);
    k_var<<<DHWSZ/128, 128>>>(dv);
    k_conv<<<dim3(HH/HT, DDEP/DT, CSPLIT), CONV_THREADS>>>(wgt);
    k_post<<<HWSZ/128, 128>>>(dv, out);
}

// round 8
// speedup vs baseline: 1.0577x; 1.0577x over previous
#include <cuda_runtime.h>
#include <cuda_fp16.h>

#define NV 5
#define NS 4
#define CC 32
#define HH 128
#define WW 160
#define DDEP 48
#define HWSZ (HH*WW)          // 20480
#define DHWSZ (DDEP*HWSZ)     // 983040

// conv tiling
#define HT 4
#define HS 6
#define DT 8
#define DS 10
#define WP 168
#define CONV_THREADS 160
#define CSPLIT 4
#define CPB (CC/CSPLIT)       // 8 channels per block

// ---------------- scratch ----------------------------------------------------
__device__ float g_rot[NS][9];
__device__ float g_trans[NS][3];
__device__ __half g_feaH[NV*HWSZ*CC];           // (view, h, w, c) fp16, 6.5 MB
__device__ float g_var[(size_t)CC*DHWSZ];       // planar (c, d,h,w)
__device__ float g_costp[CSPLIT][DHWSZ];        // partial costs

// ---------------- packed f32x2 helpers --------------------------------------
__device__ __forceinline__ unsigned long long pk2(float lo, float hi) {
    unsigned long long p;
    asm("mov.b64 %0, {%1, %2};" : "=l"(p) : "f"(lo), "f"(hi));
    return p;
}
__device__ __forceinline__ unsigned long long fma2(unsigned long long a,
                                                   unsigned long long b,
                                                   unsigned long long c) {
    unsigned long long d;
    asm("fma.rn.f32x2 %0, %1, %2, %3;" : "=l"(d) : "l"(a), "l"(b), "l"(c));
    return d;
}
__device__ __forceinline__ unsigned long long mul2(unsigned long long a,
                                                   unsigned long long b) {
    unsigned long long d;
    asm("mul.rn.f32x2 %0, %1, %2;" : "=l"(d) : "l"(a), "l"(b));
    return d;
}
__device__ __forceinline__ unsigned long long add2(unsigned long long a,
                                                   unsigned long long b) {
    unsigned long long d;
    asm("add.rn.f32x2 %0, %1, %2;" : "=l"(d) : "l"(a), "l"(b));
    return d;
}
__device__ __forceinline__ void upk2(unsigned long long p, float& lo, float& hi) {
    asm("mov.b64 {%0, %1}, %2;" : "=f"(lo), "=f"(hi) : "l"(p));
}
// half2 (as u32) -> packed f32x2
__device__ __forceinline__ unsigned long long h2_to_f32x2(unsigned int h) {
    float2 f = __half22float2(*reinterpret_cast<const __half2*>(&h));
    return pk2(f.x, f.y);
}

// ---------------- kernel 0: projection setup (1 thread, fp32) ---------------
__global__ void k_setup(const float* __restrict__ pm) {
    if (threadIdx.x != 0 || blockIdx.x != 0) return;
    float fused[NV][16];
    for (int n = 0; n < NV; n++) {
        const float* p0 = pm + n * 32;
        const float* p1 = p0 + 16;
        for (int i = 0; i < 16; i++) fused[n][i] = p0[i];
        for (int i = 0; i < 3; i++)
            for (int j = 0; j < 4; j++) {
                float s = 0.0f;
                for (int k = 0; k < 3; k++) s += p1[i*4+k] * p0[k*4+j];
                fused[n][i*4+j] = s;
            }
    }
    float a[4][8];
    for (int i = 0; i < 4; i++)
        for (int j = 0; j < 4; j++) {
            a[i][j]   = fused[0][i*4+j];
            a[i][j+4] = (i == j) ? 1.0f : 0.0f;
        }
    for (int col = 0; col < 4; col++) {
        int piv = col;
        for (int r = col + 1; r < 4; r++)
            if (fabsf(a[r][col]) > fabsf(a[piv][col])) piv = r;
        if (piv != col)
            for (int j = 0; j < 8; j++) { float t = a[col][j]; a[col][j] = a[piv][j]; a[piv][j] = t; }
        float d = a[col][col];
        for (int j = 0; j < 8; j++) a[col][j] /= d;
        for (int r = 0; r < 4; r++) {
            if (r == col) continue;
            float f = a[r][col];
            for (int j = 0; j < 8; j++) a[r][j] -= f * a[col][j];
        }
    }
    float inv[16];
    for (int i = 0; i < 4; i++)
        for (int j = 0; j < 4; j++) inv[i*4+j] = a[i][j+4];

    for (int v = 1; v < NV; v++) {
        float P[16];
        for (int i = 0; i < 4; i++)
            for (int j = 0; j < 4; j++) {
                float s = 0.0f;
                for (int k = 0; k < 4; k++) s += fused[v][i*4+k] * inv[k*4+j];
                P[i*4+j] = s;
            }
        for (int i = 0; i < 3; i++)
            for (int j = 0; j < 3; j++) g_rot[v-1][i*3+j] = P[i*4+j];
        for (int i = 0; i < 3; i++) g_trans[v-1][i] = P[i*4+3];
    }
}

// ---------------- kernel 1: transpose (N,C,H,W) fp32 -> (N,HW,C) fp16 -------
__global__ void k_transpose(const float* __restrict__ f) {
    __shared__ float tile[32][33];
    int n  = blockIdx.z;
    int p0 = blockIdx.x * 32;
    int tx = threadIdx.x, ty = threadIdx.y;
    tile[ty][tx] = f[((size_t)(n*CC + ty))*HWSZ + p0 + tx];
    __syncthreads();
    g_feaH[((size_t)(n*HWSZ + p0 + ty))*CC + tx] = __float2half(tile[tx][ty]);
}

// ---------------- kernel 2: warp + variance, fp16 gather + f32x2 math -------
__global__ void __launch_bounds__(128) k_var(const float* __restrict__ dv) {
    __shared__ int4   s_idx[4][4][32];
    __shared__ float4 s_wt [4][4][32];
    __shared__ int    s_hw [4][32];
    __shared__ float  s_var[128*33];

    const int tid  = threadIdx.x;
    const int warp = tid >> 5;
    const int lane = tid & 31;
    const int gblock = blockIdx.x * 128;

    {
        int g  = gblock + tid;
        int d  = g / HWSZ;
        int hw = g - d * HWSZ;
        int h  = hw / WW;
        int w  = hw - h * WW;
        float fx = (float)w, fy = (float)h;
        float depth = __ldg(dv + d);
        #pragma unroll
        for (int v = 0; v < NS; v++) {
            float r0 = g_rot[v][0], r1 = g_rot[v][1], r2 = g_rot[v][2];
            float r3 = g_rot[v][3], r4 = g_rot[v][4], r5 = g_rot[v][5];
            float r6 = g_rot[v][6], r7 = g_rot[v][7], r8 = g_rot[v][8];
            float t0 = g_trans[v][0], t1 = g_trans[v][1], t2 = g_trans[v][2];
            float rx = r0*fx + r1*fy + r2;
            float ry = r3*fx + r4*fy + r5;
            float rz = r6*fx + r7*fy + r8;
            float X = rx*depth + t0;
            float Y = ry*depth + t1;
            float Z = rz*depth + t2;
            float px = X / Z;
            float py = Y / Z;
            float x0 = floorf(px), y0 = floorf(py);
            float x1 = x0 + 1.0f,  y1 = y0 + 1.0f;
            float wx1 = px - x0, wx0 = 1.0f - wx1;
            float wy1 = py - y0, wy0 = 1.0f - wy1;
            bool vx0 = (x0 >= 0.0f) && (x0 <= (float)(WW-1));
            bool vx1 = (x1 >= 0.0f) && (x1 <= (float)(WW-1));
            bool vy0 = (y0 >= 0.0f) && (y0 <= (float)(HH-1));
            bool vy1 = (y1 >= 0.0f) && (y1 <= (float)(HH-1));
            int cx0 = (int)fminf(fmaxf(x0, 0.0f), (float)(WW-1));
            int cx1 = (int)fminf(fmaxf(x1, 0.0f), (float)(WW-1));
            int cy0 = (int)fminf(fmaxf(y0, 0.0f), (float)(HH-1));
            int cy1 = (int)fminf(fmaxf(y1, 0.0f), (float)(HH-1));
            int4 id;
            id.x = cy0*WW + cx0;
            id.y = cy0*WW + cx1;
            id.z = cy1*WW + cx0;
            id.w = cy1*WW + cx1;
            float4 wt;
            wt.x = wx0*wy0 * ((vx0 && vy0) ? 1.0f : 0.0f);
            wt.y = wx1*wy0 * ((vx1 && vy0) ? 1.0f : 0.0f);
            wt.z = wx0*wy1 * ((vx0 && vy1) ? 1.0f : 0.0f);
            wt.w = wx1*wy1 * ((vx1 && vy1) ? 1.0f : 0.0f);
            s_idx[warp][v][lane] = id;
            s_wt [warp][v][lane] = wt;
        }
        s_hw[warp][lane] = hw;
    }
    __syncwarp();

    const int cg = lane & 7;
    const int q  = lane >> 3;
    const uint2* fH = (const uint2*)g_feaH;   // 8B = 4 fp16 channels
    const float invN = 1.0f / (float)NV;

    #pragma unroll
    for (int it = 0; it < 8; it++) {
        int pt  = it*4 + q;
        int hw2 = s_hw[warp][pt];
        uint2 rf = fH[(size_t)hw2*8 + cg];
        unsigned long long s0 = h2_to_f32x2(rf.x);
        unsigned long long s1 = h2_to_f32x2(rf.y);
        unsigned long long q0 = mul2(s0, s0);
        unsigned long long q1 = mul2(s1, s1);
        #pragma unroll
        for (int v = 0; v < NS; v++) {
            int4   id = s_idx[warp][v][pt];
            float4 wt = s_wt [warp][v][pt];
            const uint2* fv = fH + (size_t)(v+1)*HWSZ*8;
            uint2 u00 = fv[(size_t)id.x*8 + cg];
            uint2 u01 = fv[(size_t)id.y*8 + cg];
            uint2 u10 = fv[(size_t)id.z*8 + cg];
            uint2 u11 = fv[(size_t)id.w*8 + cg];
            unsigned long long w0 = pk2(wt.x, wt.x);
            unsigned long long w1 = pk2(wt.y, wt.y);
            unsigned long long w2 = pk2(wt.z, wt.z);
            unsigned long long w3 = pk2(wt.w, wt.w);
            unsigned long long v0 = fma2(h2_to_f32x2(u00.x), w0,
                                    fma2(h2_to_f32x2(u01.x), w1,
                                    fma2(h2_to_f32x2(u10.x), w2,
                                    mul2(h2_to_f32x2(u11.x), w3))));
            unsigned long long v1 = fma2(h2_to_f32x2(u00.y), w0,
                                    fma2(h2_to_f32x2(u01.y), w1,
                                    fma2(h2_to_f32x2(u10.y), w2,
                                    mul2(h2_to_f32x2(u11.y), w3))));
            s0 = add2(s0, v0);
            s1 = add2(s1, v1);
            q0 = fma2(v0, v0, q0);
            q1 = fma2(v1, v1, q1);
        }
        float sx, sy, sz, sw, qx, qy, qz, qw;
        upk2(s0, sx, sy); upk2(s1, sz, sw);
        upk2(q0, qx, qy); upk2(q1, qz, qw);
        float mx = sx*invN, my = sy*invN, mz = sz*invN, mw = sw*invN;
        float vrx = qx*invN - mx*mx;
        float vry = qy*invN - my*my;
        float vrz = qz*invN - mz*mz;
        float vrw = qw*invN - mw*mw;
        int sbase = (warp*32 + pt)*33 + cg*4;
        s_var[sbase+0] = vrx;
        s_var[sbase+1] = vry;
        s_var[sbase+2] = vrz;
        s_var[sbase+3] = vrw;
    }
    __syncthreads();

    int gg = gblock + tid;
    #pragma unroll
    for (int c = 0; c < CC; c++)
        g_var[(size_t)c*DHWSZ + gg] = s_var[tid*33 + c];
}

// ---------------- kernel 3: 3x3x3 conv, 8 channels per block (4-way split) --
__global__ void __launch_bounds__(CONV_THREADS) k_conv(const float* __restrict__ wgt) {
    __shared__ float slab[HS][DS][WP];
    __shared__ unsigned long long wpk[CPB*27];

    const int tid = threadIdx.x;
    const int h0  = blockIdx.x * HT;
    const int d0  = blockIdx.y * DT;
    const int c0  = blockIdx.z * CPB;
    float* __restrict__ outbuf = g_costp[blockIdx.z];
    const int wg  = tid % 40;
    const int hl  = tid / 40;
    const int w0  = wg * 4;

    for (int i = tid; i < CPB*27; i += CONV_THREADS) {
        float k = __ldg(wgt + c0*27 + i);
        wpk[i] = pk2(k, k);
    }
    for (int i = tid; i < HS*DS; i += CONV_THREADS) {
        int shy = i / DS, sdd = i % DS;
        float* row = &slab[shy][sdd][0];
        row[0] = 0.f; row[1] = 0.f; row[2] = 0.f; row[3] = 0.f;
        row[164] = 0.f; row[165] = 0.f; row[166] = 0.f; row[167] = 0.f;
    }

    unsigned long long A[DT][2];
    #pragma unroll
    for (int od = 0; od < DT; od++) { A[od][0] = 0ull; A[od][1] = 0ull; }

    #pragma unroll 1
    for (int c = 0; c < CPB; c++) {
        __syncthreads();

        const float* __restrict__ vc = g_var + (size_t)(c0 + c) * DHWSZ;
        #pragma unroll
        for (int r = 0; r < 15; r++) {
            int idx = r*CONV_THREADS + tid;
            int row = idx / 40;
            int w4  = (idx % 40) * 4;
            int shy = row / DS;
            int sdd = row - shy*DS;
            int dd  = d0 - 1 + sdd;
            int hy  = h0 - 1 + shy;
            float4 v = make_float4(0.f, 0.f, 0.f, 0.f);
            if (dd >= 0 && dd < DDEP && hy >= 0 && hy < HH)
                v = *(const float4*)(vc + (size_t)dd*HWSZ + hy*WW + w4);
            *(float4*)&slab[shy][sdd][w4 + 4] = v;
        }
        __syncthreads();

        const unsigned long long* wc = wpk + c*27;
        #pragma unroll
        for (int dy = 0; dy < 3; dy++) {
            unsigned long long k00 = wc[(0*3+dy)*3+0], k01 = wc[(0*3+dy)*3+1], k02 = wc[(0*3+dy)*3+2];
            unsigned long long k10 = wc[(1*3+dy)*3+0], k11 = wc[(1*3+dy)*3+1], k12 = wc[(1*3+dy)*3+2];
            unsigned long long k20 = wc[(2*3+dy)*3+0], k21 = wc[(2*3+dy)*3+1], k22 = wc[(2*3+dy)*3+2];
            const float* hrow = &slab[hl + dy][0][0];
            #pragma unroll
            for (int sdd = 0; sdd < DS; sdd++) {
                const float* col = hrow + sdd*WP;
                float4 a = *(const float4*)(col + w0 + 4);
                float2 l = *(const float2*)(col + w0 + 2);
                float2 rr = *(const float2*)(col + w0 + 8);
                unsigned long long P0 = pk2(l.y,  a.x);
                unsigned long long P1 = pk2(a.x,  a.y);
                unsigned long long P2 = pk2(a.y,  a.z);
                unsigned long long P3 = pk2(a.z,  a.w);
                unsigned long long P4 = pk2(a.w,  rr.x);
                #pragma unroll
                for (int dz = 0; dz < 3; dz++) {
                    int od = sdd - dz;
                    if (od < 0 || od >= DT) continue;
                    unsigned long long q0 = (dz==0) ? k00 : (dz==1) ? k10 : k20;
                    unsigned long long q1 = (dz==0) ? k01 : (dz==1) ? k11 : k21;
                    unsigned long long q2 = (dz==0) ? k02 : (dz==1) ? k12 : k22;
                    A[od][0] = fma2(P0, q0, A[od][0]);
                    A[od][0] = fma2(P1, q1, A[od][0]);
                    A[od][0] = fma2(P2, q2, A[od][0]);
                    A[od][1] = fma2(P2, q0, A[od][1]);
                    A[od][1] = fma2(P3, q1, A[od][1]);
                    A[od][1] = fma2(P4, q2, A[od][1]);
                }
            }
        }
    }

    const int ob = (h0 + hl)*WW + w0;
    #pragma unroll
    for (int od = 0; od < DT; od++) {
        float o0, o1, o2, o3;
        upk2(A[od][0], o0, o1);
        upk2(A[od][1], o2, o3);
        float4 v = make_float4(o0, o1, o2, o3);
        *(float4*)(outbuf + (size_t)(d0 + od)*HWSZ + ob) = v;
    }
}

// ---------------- kernel 4: softmax / depth / confidence --------------------
__global__ void __launch_bounds__(128) k_post(const float* __restrict__ dv,
                                              float* __restrict__ out) {
    int pix = blockIdx.x * 128 + threadIdx.x;
    float p[DDEP];
    float mx = -1e30f;
    #pragma unroll
    for (int d = 0; d < DDEP; d++) {
        size_t o = (size_t)d*HWSZ + pix;
        p[d] = (g_costp[0][o] + g_costp[1][o]) + (g_costp[2][o] + g_costp[3][o]);
        mx = fmaxf(mx, p[d]);
    }
    float s = 0.0f;
    #pragma unroll
    for (int d = 0; d < DDEP; d++) { p[d] = expf(p[d] - mx); s += p[d]; }
    float inv = 1.0f / s;
    float depth = 0.0f, didx = 0.0f;
    #pragma unroll
    for (int d = 0; d < DDEP; d++) {
        float pr = p[d] * inv;
        p[d] = pr;
        depth += pr * __ldg(dv + d);
        didx  += pr * (float)d;
    }
    int di = (int)didx;
    di = min(max(di, 0), DDEP - 1);
    float conf = 0.0f;
    #pragma unroll
    for (int d = 0; d < DDEP; d++) {
        bool inwin = (d >= di - 1) && (d <= di + 2);
        conf += inwin ? p[d] : 0.0f;
    }
    out[pix]        = depth;
    out[HWSZ + pix] = conf;
}

// ---------------- launcher ---------------------------------------------------
extern "C" void kernel_launch(void* const* d_in, const int* in_sizes, int n_in,
                              void* d_out, int out_size) {
    const float* features = nullptr;
    const float* pm       = nullptr;
    const float* dv       = nullptr;
    const float* wgt      = nullptr;
    for (int i = 0; i < n_in; i++) {
        switch (in_sizes[i]) {
            case NV*CC*HWSZ: features = (const float*)d_in[i]; break;
            case 160:        pm       = (const float*)d_in[i]; break;
            case 48:         dv       = (const float*)d_in[i]; break;
            case 864:        wgt      = (const float*)d_in[i]; break;
            default: break;
        }
    }
    if (!features) features = (const float*)d_in[0];
    if (!pm)       pm       = (const float*)d_in[1];
    if (!dv)       dv       = (const float*)d_in[2];
    if (!wgt)      wgt      = (const float*)d_in[3];
    float* out = (float*)d_out;

    k_setup<<<1, 32>>>(pm);
    k_transpose<<<dim3(HWSZ/32, 1, NV), dim3(32, 32)>>>(features);
    k_var<<<DHWSZ/128, 128>>>(dv);
    k_conv<<<dim3(HH/HT, DDEP/DT, CSPLIT), CONV_THREADS>>>(wgt);
    k_post<<<HWSZ/128, 128>>>(dv, out);
}

// round 9
// speedup vs baseline: 1.2083x; 1.1425x over previous
#include <cuda_runtime.h>
#include <cuda_fp16.h>

#define NV 5
#define NS 4
#define CC 32
#define HH 128
#define WW 160
#define DDEP 48
#define HWSZ (HH*WW)          // 20480
#define DHWSZ (DDEP*HWSZ)     // 983040

// conv tiling
#define HT 4
#define HS 6
#define DT 8
#define DS 10
#define WP 168
#define CONV_THREADS 160
#define CSPLIT 4
#define CPB (CC/CSPLIT)       // 8 channels per block

// ---------------- scratch ----------------------------------------------------
__device__ float g_rot[NS][9];
__device__ float g_trans[NS][3];
__device__ __half g_feaH[NV*HWSZ*CC];           // (view, h, w, c) fp16, 6.5 MB
__device__ float g_var[(size_t)CC*DHWSZ];       // planar (c, d,h,w)
__device__ float g_costp[CSPLIT][DHWSZ];        // partial costs

// ---------------- packed f32x2 helpers --------------------------------------
__device__ __forceinline__ unsigned long long pk2(float lo, float hi) {
    unsigned long long p;
    asm("mov.b64 %0, {%1, %2};" : "=l"(p) : "f"(lo), "f"(hi));
    return p;
}
__device__ __forceinline__ unsigned long long fma2(unsigned long long a,
                                                   unsigned long long b,
                                                   unsigned long long c) {
    unsigned long long d;
    asm("fma.rn.f32x2 %0, %1, %2, %3;" : "=l"(d) : "l"(a), "l"(b), "l"(c));
    return d;
}
__device__ __forceinline__ unsigned long long mul2(unsigned long long a,
                                                   unsigned long long b) {
    unsigned long long d;
    asm("mul.rn.f32x2 %0, %1, %2;" : "=l"(d) : "l"(a), "l"(b));
    return d;
}
__device__ __forceinline__ unsigned long long add2(unsigned long long a,
                                                   unsigned long long b) {
    unsigned long long d;
    asm("add.rn.f32x2 %0, %1, %2;" : "=l"(d) : "l"(a), "l"(b));
    return d;
}
__device__ __forceinline__ void upk2(unsigned long long p, float& lo, float& hi) {
    asm("mov.b64 {%0, %1}, %2;" : "=f"(lo), "=f"(hi) : "l"(p));
}
__device__ __forceinline__ __half2 u2h(unsigned int x) {
    return *reinterpret_cast<__half2*>(&x);
}
// fp16 bilinear for one half2 word; result as packed f32x2
__device__ __forceinline__ unsigned long long interp_word(
    unsigned int a00, unsigned int a01, unsigned int a10, unsigned int a11,
    unsigned int w0,  unsigned int w1,  unsigned int w2,  unsigned int w3)
{
    __half2 v = __hmul2(u2h(a11), u2h(w3));
    v = __hfma2(u2h(a10), u2h(w2), v);
    v = __hfma2(u2h(a01), u2h(w1), v);
    v = __hfma2(u2h(a00), u2h(w0), v);
    float2 f = __half22float2(v);
    return pk2(f.x, f.y);
}

// ---------------- kernel 0: projection setup (1 thread, fp32) ---------------
__global__ void k_setup(const float* __restrict__ pm) {
    if (threadIdx.x != 0 || blockIdx.x != 0) return;
    float fused[NV][16];
    for (int n = 0; n < NV; n++) {
        const float* p0 = pm + n * 32;
        const float* p1 = p0 + 16;
        for (int i = 0; i < 16; i++) fused[n][i] = p0[i];
        for (int i = 0; i < 3; i++)
            for (int j = 0; j < 4; j++) {
                float s = 0.0f;
                for (int k = 0; k < 3; k++) s += p1[i*4+k] * p0[k*4+j];
                fused[n][i*4+j] = s;
            }
    }
    float a[4][8];
    for (int i = 0; i < 4; i++)
        for (int j = 0; j < 4; j++) {
            a[i][j]   = fused[0][i*4+j];
            a[i][j+4] = (i == j) ? 1.0f : 0.0f;
        }
    for (int col = 0; col < 4; col++) {
        int piv = col;
        for (int r = col + 1; r < 4; r++)
            if (fabsf(a[r][col]) > fabsf(a[piv][col])) piv = r;
        if (piv != col)
            for (int j = 0; j < 8; j++) { float t = a[col][j]; a[col][j] = a[piv][j]; a[piv][j] = t; }
        float d = a[col][col];
        for (int j = 0; j < 8; j++) a[col][j] /= d;
        for (int r = 0; r < 4; r++) {
            if (r == col) continue;
            float f = a[r][col];
            for (int j = 0; j < 8; j++) a[r][j] -= f * a[col][j];
        }
    }
    float inv[16];
    for (int i = 0; i < 4; i++)
        for (int j = 0; j < 4; j++) inv[i*4+j] = a[i][j+4];

    for (int v = 1; v < NV; v++) {
        float P[16];
        for (int i = 0; i < 4; i++)
            for (int j = 0; j < 4; j++) {
                float s = 0.0f;
                for (int k = 0; k < 4; k++) s += fused[v][i*4+k] * inv[k*4+j];
                P[i*4+j] = s;
            }
        for (int i = 0; i < 3; i++)
            for (int j = 0; j < 3; j++) g_rot[v-1][i*3+j] = P[i*4+j];
        for (int i = 0; i < 3; i++) g_trans[v-1][i] = P[i*4+3];
    }
}

// ---------------- kernel 1: transpose (N,C,H,W) fp32 -> (N,HW,C) fp16 -------
__global__ void k_transpose(const float* __restrict__ f) {
    __shared__ float tile[32][33];
    int n  = blockIdx.z;
    int p0 = blockIdx.x * 32;
    int tx = threadIdx.x, ty = threadIdx.y;
    tile[ty][tx] = f[((size_t)(n*CC + ty))*HWSZ + p0 + tx];
    __syncthreads();
    g_feaH[((size_t)(n*HWSZ + p0 + ty))*CC + tx] = __float2half(tile[tx][ty]);
}

// ---------------- kernel 2: warp + variance, HFMA2 interp + f32x2 accum -----
__global__ void __launch_bounds__(128) k_var(const float* __restrict__ dv) {
    __shared__ int4  s_idx[4][4][32];
    __shared__ uint4 s_wth[4][4][32];   // {w,w} half2 x4 per (point, view)
    __shared__ int   s_hw [4][32];
    __shared__ float s_var[128*33];

    const int tid  = threadIdx.x;
    const int warp = tid >> 5;
    const int lane = tid & 31;
    const int gblock = blockIdx.x * 128;

    // ---- phase 1: per-thread projection descriptors for one point ----
    {
        int g  = gblock + tid;
        int d  = g / HWSZ;
        int hw = g - d * HWSZ;
        int h  = hw / WW;
        int w  = hw - h * WW;
        float fx = (float)w, fy = (float)h;
        float depth = __ldg(dv + d);
        #pragma unroll
        for (int v = 0; v < NS; v++) {
            float r0 = g_rot[v][0], r1 = g_rot[v][1], r2 = g_rot[v][2];
            float r3 = g_rot[v][3], r4 = g_rot[v][4], r5 = g_rot[v][5];
            float r6 = g_rot[v][6], r7 = g_rot[v][7], r8 = g_rot[v][8];
            float t0 = g_trans[v][0], t1 = g_trans[v][1], t2 = g_trans[v][2];
            float rx = r0*fx + r1*fy + r2;
            float ry = r3*fx + r4*fy + r5;
            float rz = r6*fx + r7*fy + r8;
            float X = rx*depth + t0;
            float Y = ry*depth + t1;
            float Z = rz*depth + t2;
            float px = __fdividef(X, Z);
            float py = __fdividef(Y, Z);
            float x0 = floorf(px), y0 = floorf(py);
            float x1 = x0 + 1.0f,  y1 = y0 + 1.0f;
            float wx1 = px - x0, wx0 = 1.0f - wx1;
            float wy1 = py - y0, wy0 = 1.0f - wy1;
            bool vx0 = (x0 >= 0.0f) && (x0 <= (float)(WW-1));
            bool vx1 = (x1 >= 0.0f) && (x1 <= (float)(WW-1));
            bool vy0 = (y0 >= 0.0f) && (y0 <= (float)(HH-1));
            bool vy1 = (y1 >= 0.0f) && (y1 <= (float)(HH-1));
            int cx0 = (int)fminf(fmaxf(x0, 0.0f), (float)(WW-1));
            int cx1 = (int)fminf(fmaxf(x1, 0.0f), (float)(WW-1));
            int cy0 = (int)fminf(fmaxf(y0, 0.0f), (float)(HH-1));
            int cy1 = (int)fminf(fmaxf(y1, 0.0f), (float)(HH-1));
            int4 id;
            id.x = cy0*WW + cx0;
            id.y = cy0*WW + cx1;
            id.z = cy1*WW + cx0;
            id.w = cy1*WW + cx1;
            float w00 = wx0*wy0 * ((vx0 && vy0) ? 1.0f : 0.0f);
            float w01 = wx1*wy0 * ((vx1 && vy0) ? 1.0f : 0.0f);
            float w10 = wx0*wy1 * ((vx0 && vy1) ? 1.0f : 0.0f);
            float w11 = wx1*wy1 * ((vx1 && vy1) ? 1.0f : 0.0f);
            __half2 h0 = __float2half2_rn(w00);
            __half2 h1 = __float2half2_rn(w01);
            __half2 h2 = __float2half2_rn(w10);
            __half2 h3 = __float2half2_rn(w11);
            uint4 wh;
            wh.x = *reinterpret_cast<unsigned int*>(&h0);
            wh.y = *reinterpret_cast<unsigned int*>(&h1);
            wh.z = *reinterpret_cast<unsigned int*>(&h2);
            wh.w = *reinterpret_cast<unsigned int*>(&h3);
            s_idx[warp][v][lane] = id;
            s_wth[warp][v][lane] = wh;
        }
        s_hw[warp][lane] = hw;
    }
    __syncwarp();

    // ---- phase 2: lanes = (cg 0..3 x q 0..7); 8 channels per thread --------
    const int cg = lane & 3;          // uint4 = 8 fp16 channels
    const int q  = lane >> 2;
    const uint4* fH4 = (const uint4*)g_feaH;   // pixel stride = 4 uint4
    const float invN = 1.0f / (float)NV;

    #pragma unroll
    for (int it = 0; it < 4; it++) {
        int pt  = it*8 + q;
        int hw2 = s_hw[warp][pt];
        uint4 rf = fH4[(size_t)hw2*4 + cg];
        unsigned long long s0, s1, s2, s3;
        {
            float2 f;
            f = __half22float2(u2h(rf.x)); s0 = pk2(f.x, f.y);
            f = __half22float2(u2h(rf.y)); s1 = pk2(f.x, f.y);
            f = __half22float2(u2h(rf.z)); s2 = pk2(f.x, f.y);
            f = __half22float2(u2h(rf.w)); s3 = pk2(f.x, f.y);
        }
        unsigned long long q0 = mul2(s0, s0);
        unsigned long long q1 = mul2(s1, s1);
        unsigned long long q2 = mul2(s2, s2);
        unsigned long long q3 = mul2(s3, s3);
        #pragma unroll
        for (int v = 0; v < NS; v++) {
            int4  id = s_idx[warp][v][pt];
            uint4 wh = s_wth[warp][v][pt];
            const uint4* fv = fH4 + (size_t)(v+1)*HWSZ*4;
            uint4 c00 = fv[(size_t)id.x*4 + cg];
            uint4 c01 = fv[(size_t)id.y*4 + cg];
            uint4 c10 = fv[(size_t)id.z*4 + cg];
            uint4 c11 = fv[(size_t)id.w*4 + cg];
            unsigned long long v0 = interp_word(c00.x, c01.x, c10.x, c11.x, wh.x, wh.y, wh.z, wh.w);
            unsigned long long v1 = interp_word(c00.y, c01.y, c10.y, c11.y, wh.x, wh.y, wh.z, wh.w);
            unsigned long long v2 = interp_word(c00.z, c01.z, c10.z, c11.z, wh.x, wh.y, wh.z, wh.w);
            unsigned long long v3 = interp_word(c00.w, c01.w, c10.w, c11.w, wh.x, wh.y, wh.z, wh.w);
            s0 = add2(s0, v0); q0 = fma2(v0, v0, q0);
            s1 = add2(s1, v1); q1 = fma2(v1, v1, q1);
            s2 = add2(s2, v2); q2 = fma2(v2, v2, q2);
            s3 = add2(s3, v3); q3 = fma2(v3, v3, q3);
        }
        // finalize 8 channels
        float sa[8], qa[8];
        upk2(s0, sa[0], sa[1]); upk2(s1, sa[2], sa[3]);
        upk2(s2, sa[4], sa[5]); upk2(s3, sa[6], sa[7]);
        upk2(q0, qa[0], qa[1]); upk2(q1, qa[2], qa[3]);
        upk2(q2, qa[4], qa[5]); upk2(q3, qa[6], qa[7]);
        int sbase = (warp*32 + pt)*33 + cg*8;
        #pragma unroll
        for (int j = 0; j < 8; j++) {
            float m = sa[j] * invN;
            s_var[sbase + j] = qa[j]*invN - m*m;
        }
    }
    __syncthreads();

    // ---- planar write: g_var[c][g] ----
    int gg = gblock + tid;
    #pragma unroll
    for (int c = 0; c < CC; c++)
        g_var[(size_t)c*DHWSZ + gg] = s_var[tid*33 + c];
}

// ---------------- kernel 3: 3x3x3 conv, 8 channels per block (4-way split) --
__global__ void __launch_bounds__(CONV_THREADS) k_conv(const float* __restrict__ wgt) {
    __shared__ float slab[HS][DS][WP];
    __shared__ unsigned long long wpk[CPB*27];

    const int tid = threadIdx.x;
    const int h0  = blockIdx.x * HT;
    const int d0  = blockIdx.y * DT;
    const int c0  = blockIdx.z * CPB;
    float* __restrict__ outbuf = g_costp[blockIdx.z];
    const int wg  = tid % 40;
    const int hl  = tid / 40;
    const int w0  = wg * 4;

    for (int i = tid; i < CPB*27; i += CONV_THREADS) {
        float k = __ldg(wgt + c0*27 + i);
        wpk[i] = pk2(k, k);
    }
    for (int i = tid; i < HS*DS; i += CONV_THREADS) {
        int shy = i / DS, sdd = i % DS;
        float* row = &slab[shy][sdd][0];
        row[0] = 0.f; row[1] = 0.f; row[2] = 0.f; row[3] = 0.f;
        row[164] = 0.f; row[165] = 0.f; row[166] = 0.f; row[167] = 0.f;
    }

    unsigned long long A[DT][2];
    #pragma unroll
    for (int od = 0; od < DT; od++) { A[od][0] = 0ull; A[od][1] = 0ull; }

    #pragma unroll 1
    for (int c = 0; c < CPB; c++) {
        __syncthreads();

        const float* __restrict__ vc = g_var + (size_t)(c0 + c) * DHWSZ;
        #pragma unroll
        for (int r = 0; r < 15; r++) {
            int idx = r*CONV_THREADS + tid;
            int row = idx / 40;
            int w4  = (idx % 40) * 4;
            int shy = row / DS;
            int sdd = row - shy*DS;
            int dd  = d0 - 1 + sdd;
            int hy  = h0 - 1 + shy;
            float4 v = make_float4(0.f, 0.f, 0.f, 0.f);
            if (dd >= 0 && dd < DDEP && hy >= 0 && hy < HH)
                v = *(const float4*)(vc + (size_t)dd*HWSZ + hy*WW + w4);
            *(float4*)&slab[shy][sdd][w4 + 4] = v;
        }
        __syncthreads();

        const unsigned long long* wc = wpk + c*27;
        #pragma unroll
        for (int dy = 0; dy < 3; dy++) {
            unsigned long long k00 = wc[(0*3+dy)*3+0], k01 = wc[(0*3+dy)*3+1], k02 = wc[(0*3+dy)*3+2];
            unsigned long long k10 = wc[(1*3+dy)*3+0], k11 = wc[(1*3+dy)*3+1], k12 = wc[(1*3+dy)*3+2];
            unsigned long long k20 = wc[(2*3+dy)*3+0], k21 = wc[(2*3+dy)*3+1], k22 = wc[(2*3+dy)*3+2];
            const float* hrow = &slab[hl + dy][0][0];
            #pragma unroll
            for (int sdd = 0; sdd < DS; sdd++) {
                const float* col = hrow + sdd*WP;
                float4 a = *(const float4*)(col + w0 + 4);
                float2 l = *(const float2*)(col + w0 + 2);
                float2 rr = *(const float2*)(col + w0 + 8);
                unsigned long long P0 = pk2(l.y,  a.x);
                unsigned long long P1 = pk2(a.x,  a.y);
                unsigned long long P2 = pk2(a.y,  a.z);
                unsigned long long P3 = pk2(a.z,  a.w);
                unsigned long long P4 = pk2(a.w,  rr.x);
                #pragma unroll
                for (int dz = 0; dz < 3; dz++) {
                    int od = sdd - dz;
                    if (od < 0 || od >= DT) continue;
                    unsigned long long q0 = (dz==0) ? k00 : (dz==1) ? k10 : k20;
                    unsigned long long q1 = (dz==0) ? k01 : (dz==1) ? k11 : k21;
                    unsigned long long q2 = (dz==0) ? k02 : (dz==1) ? k12 : k22;
                    A[od][0] = fma2(P0, q0, A[od][0]);
                    A[od][0] = fma2(P1, q1, A[od][0]);
                    A[od][0] = fma2(P2, q2, A[od][0]);
                    A[od][1] = fma2(P2, q0, A[od][1]);
                    A[od][1] = fma2(P3, q1, A[od][1]);
                    A[od][1] = fma2(P4, q2, A[od][1]);
                }
            }
        }
    }

    const int ob = (h0 + hl)*WW + w0;
    #pragma unroll
    for (int od = 0; od < DT; od++) {
        float o0, o1, o2, o3;
        upk2(A[od][0], o0, o1);
        upk2(A[od][1], o2, o3);
        float4 v = make_float4(o0, o1, o2, o3);
        *(float4*)(outbuf + (size_t)(d0 + od)*HWSZ + ob) = v;
    }
}

// ---------------- kernel 4: softmax / depth / confidence --------------------
__global__ void __launch_bounds__(128) k_post(const float* __restrict__ dv,
                                              float* __restrict__ out) {
    int pix = blockIdx.x * 128 + threadIdx.x;
    float p[DDEP];
    float mx = -1e30f;
    #pragma unroll
    for (int d = 0; d < DDEP; d++) {
        size_t o = (size_t)d*HWSZ + pix;
        p[d] = (g_costp[0][o] + g_costp[1][o]) + (g_costp[2][o] + g_costp[3][o]);
        mx = fmaxf(mx, p[d]);
    }
    float s = 0.0f;
    #pragma unroll
    for (int d = 0; d < DDEP; d++) { p[d] = expf(p[d] - mx); s += p[d]; }
    float inv = 1.0f / s;
    float depth = 0.0f, didx = 0.0f;
    #pragma unroll
    for (int d = 0; d < DDEP; d++) {
        float pr = p[d] * inv;
        p[d] = pr;
        depth += pr * __ldg(dv + d);
        didx  += pr * (float)d;
    }
    int di = (int)didx;
    di = min(max(di, 0), DDEP - 1);
    float conf = 0.0f;
    #pragma unroll
    for (int d = 0; d < DDEP; d++) {
        bool inwin = (d >= di - 1) && (d <= di + 2);
        conf += inwin ? p[d] : 0.0f;
    }
    out[pix]        = depth;
    out[HWSZ + pix] = conf;
}

// ---------------- launcher ---------------------------------------------------
extern "C" void kernel_launch(void* const* d_in, const int* in_sizes, int n_in,
                              void* d_out, int out_size) {
    const float* features = nullptr;
    const float* pm       = nullptr;
    const float* dv       = nullptr;
    const float* wgt      = nullptr;
    for (int i = 0; i < n_in; i++) {
        switch (in_sizes[i]) {
            case NV*CC*HWSZ: features = (const float*)d_in[i]; break;
            case 160:        pm       = (const float*)d_in[i]; break;
            case 48:         dv       = (const float*)d_in[i]; break;
            case 864:        wgt      = (const float*)d_in[i]; break;
            default: break;
        }
    }
    if (!features) features = (const float*)d_in[0];
    if (!pm)       pm       = (const float*)d_in[1];
    if (!dv)       dv       = (const float*)d_in[2];
    if (!wgt)      wgt      = (const float*)d_in[3];
    float* out = (float*)d_out;

    k_setup<<<1, 32>>>(pm);
    k_transpose<<<dim3(HWSZ/32, 1, NV), dim3(32, 32)>>>(features);
    k_var<<<DHWSZ/128, 128>>>(dv);
    k_conv<<<dim3(HH/HT, DDEP/DT, CSPLIT), CONV_THREADS>>>(wgt);
    k_post<<<HWSZ/128, 128>>>(dv, out);
}

// round 11
// speedup vs baseline: 1.2203x; 1.0099x over previous
#include <cuda_runtime.h>
#include <cuda_fp16.h>

#define NV 5
#define NS 4
#define CC 32
#define HH 128
#define WW 160
#define DDEP 48
#define HWSZ (HH*WW)          // 20480
#define DHWSZ (DDEP*HWSZ)     // 983040

// conv tiling
#define HT 4
#define HS 6
#define DT 6
#define DS 8
#define WP 168
#define CONV_THREADS 160
#define CSPLIT 4
#define CPB (CC/CSPLIT)       // 8 channels per block

// ---------------- scratch ----------------------------------------------------
__device__ float g_rot[NS][9];
__device__ float g_trans[NS][3];
__device__ __half g_feaH[NV*HWSZ*CC];           // (view, h, w, c) fp16, 6.5 MB
__device__ float g_var[(size_t)CC*DHWSZ];       // planar (c, d,h,w)
__device__ float g_costp[CSPLIT][DHWSZ];        // partial costs

// ---------------- packed f32x2 helpers --------------------------------------
__device__ __forceinline__ unsigned long long pk2(float lo, float hi) {
    unsigned long long p;
    asm("mov.b64 %0, {%1, %2};" : "=l"(p) : "f"(lo), "f"(hi));
    return p;
}
__device__ __forceinline__ unsigned long long fma2(unsigned long long a,
                                                   unsigned long long b,
                                                   unsigned long long c) {
    unsigned long long d;
    asm("fma.rn.f32x2 %0, %1, %2, %3;" : "=l"(d) : "l"(a), "l"(b), "l"(c));
    return d;
}
__device__ __forceinline__ unsigned long long mul2(unsigned long long a,
                                                   unsigned long long b) {
    unsigned long long d;
    asm("mul.rn.f32x2 %0, %1, %2;" : "=l"(d) : "l"(a), "l"(b));
    return d;
}
__device__ __forceinline__ unsigned long long add2(unsigned long long a,
                                                   unsigned long long b) {
    unsigned long long d;
    asm("add.rn.f32x2 %0, %1, %2;" : "=l"(d) : "l"(a), "l"(b));
    return d;
}
__device__ __forceinline__ void upk2(unsigned long long p, float& lo, float& hi) {
    asm("mov.b64 {%0, %1}, %2;" : "=f"(lo), "=f"(hi) : "l"(p));
}
__device__ __forceinline__ __half2 u2h(unsigned int x) {
    return *reinterpret_cast<__half2*>(&x);
}
// fp16 bilinear for one half2 word; result as packed f32x2
__device__ __forceinline__ unsigned long long interp_word(
    unsigned int a00, unsigned int a01, unsigned int a10, unsigned int a11,
    unsigned int w0,  unsigned int w1,  unsigned int w2,  unsigned int w3)
{
    __half2 v = __hmul2(u2h(a11), u2h(w3));
    v = __hfma2(u2h(a10), u2h(w2), v);
    v = __hfma2(u2h(a01), u2h(w1), v);
    v = __hfma2(u2h(a00), u2h(w0), v);
    float2 f = __half22float2(v);
    return pk2(f.x, f.y);
}

// ---------------- kernel 0: projection setup (1 thread, fp32) ---------------
__global__ void k_setup(const float* __restrict__ pm) {
    if (threadIdx.x != 0 || blockIdx.x != 0) return;
    float fused[NV][16];
    for (int n = 0; n < NV; n++) {
        const float* p0 = pm + n * 32;
        const float* p1 = p0 + 16;
        for (int i = 0; i < 16; i++) fused[n][i] = p0[i];
        for (int i = 0; i < 3; i++)
            for (int j = 0; j < 4; j++) {
                float s = 0.0f;
                for (int k = 0; k < 3; k++) s += p1[i*4+k] * p0[k*4+j];
                fused[n][i*4+j] = s;
            }
    }
    float a[4][8];
    for (int i = 0; i < 4; i++)
        for (int j = 0; j < 4; j++) {
            a[i][j]   = fused[0][i*4+j];
            a[i][j+4] = (i == j) ? 1.0f : 0.0f;
        }
    for (int col = 0; col < 4; col++) {
        int piv = col;
        for (int r = col + 1; r < 4; r++)
            if (fabsf(a[r][col]) > fabsf(a[piv][col])) piv = r;
        if (piv != col)
            for (int j = 0; j < 8; j++) { float t = a[col][j]; a[col][j] = a[piv][j]; a[piv][j] = t; }
        float d = a[col][col];
        for (int j = 0; j < 8; j++) a[col][j] /= d;
        for (int r = 0; r < 4; r++) {
            if (r == col) continue;
            float f = a[r][col];
            for (int j = 0; j < 8; j++) a[r][j] -= f * a[col][j];
        }
    }
    float inv[16];
    for (int i = 0; i < 4; i++)
        for (int j = 0; j < 4; j++) inv[i*4+j] = a[i][j+4];

    for (int v = 1; v < NV; v++) {
        float P[16];
        for (int i = 0; i < 4; i++)
            for (int j = 0; j < 4; j++) {
                float s = 0.0f;
                for (int k = 0; k < 4; k++) s += fused[v][i*4+k] * inv[k*4+j];
                P[i*4+j] = s;
            }
        for (int i = 0; i < 3; i++)
            for (int j = 0; j < 3; j++) g_rot[v-1][i*3+j] = P[i*4+j];
        for (int i = 0; i < 3; i++) g_trans[v-1][i] = P[i*4+3];
    }
}

// ---------------- kernel 1: transpose (N,C,H,W) fp32 -> (N,HW,C) fp16 -------
__global__ void k_transpose(const float* __restrict__ f) {
    __shared__ float tile[32][33];
    int n  = blockIdx.z;
    int p0 = blockIdx.x * 32;
    int tx = threadIdx.x, ty = threadIdx.y;
    tile[ty][tx] = f[((size_t)(n*CC + ty))*HWSZ + p0 + tx];
    __syncthreads();
    g_feaH[((size_t)(n*HWSZ + p0 + ty))*CC + tx] = __float2half(tile[tx][ty]);
}

// ---------------- kernel 2: warp + variance, HFMA2 interp + f32x2 accum -----
__global__ void __launch_bounds__(128) k_var(const float* __restrict__ dv) {
    __shared__ int4  s_idx[4][4][32];
    __shared__ uint4 s_wth[4][4][32];   // {w,w} half2 x4 per (point, view)
    __shared__ int   s_hw [4][32];
    __shared__ float s_var[128*33];

    const int tid  = threadIdx.x;
    const int warp = tid >> 5;
    const int lane = tid & 31;
    const int gblock = blockIdx.x * 128;

    // ---- phase 1: per-thread projection descriptors for one point ----
    {
        int g  = gblock + tid;
        int d  = g / HWSZ;
        int hw = g - d * HWSZ;
        int h  = hw / WW;
        int w  = hw - h * WW;
        float fx = (float)w, fy = (float)h;
        float depth = __ldg(dv + d);
        #pragma unroll
        for (int v = 0; v < NS; v++) {
            float r0 = g_rot[v][0], r1 = g_rot[v][1], r2 = g_rot[v][2];
            float r3 = g_rot[v][3], r4 = g_rot[v][4], r5 = g_rot[v][5];
            float r6 = g_rot[v][6], r7 = g_rot[v][7], r8 = g_rot[v][8];
            float t0 = g_trans[v][0], t1 = g_trans[v][1], t2 = g_trans[v][2];
            float rx = r0*fx + r1*fy + r2;
            float ry = r3*fx + r4*fy + r5;
            float rz = r6*fx + r7*fy + r8;
            float X = rx*depth + t0;
            float Y = ry*depth + t1;
            float Z = rz*depth + t2;
            float px = __fdividef(X, Z);
            float py = __fdividef(Y, Z);
            float x0 = floorf(px), y0 = floorf(py);
            float x1 = x0 + 1.0f,  y1 = y0 + 1.0f;
            float wx1 = px - x0, wx0 = 1.0f - wx1;
            float wy1 = py - y0, wy0 = 1.0f - wy1;
            bool vx0 = (x0 >= 0.0f) && (x0 <= (float)(WW-1));
            bool vx1 = (x1 >= 0.0f) && (x1 <= (float)(WW-1));
            bool vy0 = (y0 >= 0.0f) && (y0 <= (float)(HH-1));
            bool vy1 = (y1 >= 0.0f) && (y1 <= (float)(HH-1));
            int cx0 = (int)fminf(fmaxf(x0, 0.0f), (float)(WW-1));
            int cx1 = (int)fminf(fmaxf(x1, 0.0f), (float)(WW-1));
            int cy0 = (int)fminf(fmaxf(y0, 0.0f), (float)(HH-1));
            int cy1 = (int)fminf(fmaxf(y1, 0.0f), (float)(HH-1));
            int4 id;
            id.x = cy0*WW + cx0;
            id.y = cy0*WW + cx1;
            id.z = cy1*WW + cx0;
            id.w = cy1*WW + cx1;
            float w00 = wx0*wy0 * ((vx0 && vy0) ? 1.0f : 0.0f);
            float w01 = wx1*wy0 * ((vx1 && vy0) ? 1.0f : 0.0f);
            float w10 = wx0*wy1 * ((vx0 && vy1) ? 1.0f : 0.0f);
            float w11 = wx1*wy1 * ((vx1 && vy1) ? 1.0f : 0.0f);
            __half2 h0 = __float2half2_rn(w00);
            __half2 h1 = __float2half2_rn(w01);
            __half2 h2 = __float2half2_rn(w10);
            __half2 h3 = __float2half2_rn(w11);
            uint4 wh;
            wh.x = *reinterpret_cast<unsigned int*>(&h0);
            wh.y = *reinterpret_cast<unsigned int*>(&h1);
            wh.z = *reinterpret_cast<unsigned int*>(&h2);
            wh.w = *reinterpret_cast<unsigned int*>(&h3);
            s_idx[warp][v][lane] = id;
            s_wth[warp][v][lane] = wh;
        }
        s_hw[warp][lane] = hw;
    }
    __syncwarp();

    // ---- phase 2: lanes = (cg 0..3 x q 0..7); 8 channels per thread --------
    const int cg = lane & 3;          // uint4 = 8 fp16 channels
    const int q  = lane >> 2;
    const uint4* fH4 = (const uint4*)g_feaH;   // pixel stride = 4 uint4
    const float invN = 1.0f / (float)NV;

    #pragma unroll
    for (int it = 0; it < 4; it++) {
        int pt  = it*8 + q;
        int hw2 = s_hw[warp][pt];
        uint4 rf = fH4[(size_t)hw2*4 + cg];
        unsigned long long s0, s1, s2, s3;
        {
            float2 f;
            f = __half22float2(u2h(rf.x)); s0 = pk2(f.x, f.y);
            f = __half22float2(u2h(rf.y)); s1 = pk2(f.x, f.y);
            f = __half22float2(u2h(rf.z)); s2 = pk2(f.x, f.y);
            f = __half22float2(u2h(rf.w)); s3 = pk2(f.x, f.y);
        }
        unsigned long long q0 = mul2(s0, s0);
        unsigned long long q1 = mul2(s1, s1);
        unsigned long long q2 = mul2(s2, s2);
        unsigned long long q3 = mul2(s3, s3);
        #pragma unroll
        for (int v = 0; v < NS; v++) {
            int4  id = s_idx[warp][v][pt];
            uint4 wh = s_wth[warp][v][pt];
            const uint4* fv = fH4 + (size_t)(v+1)*HWSZ*4;
            uint4 c00 = fv[(size_t)id.x*4 + cg];
            uint4 c01 = fv[(size_t)id.y*4 + cg];
            uint4 c10 = fv[(size_t)id.z*4 + cg];
            uint4 c11 = fv[(size_t)id.w*4 + cg];
            unsigned long long v0 = interp_word(c00.x, c01.x, c10.x, c11.x, wh.x, wh.y, wh.z, wh.w);
            unsigned long long v1 = interp_word(c00.y, c01.y, c10.y, c11.y, wh.x, wh.y, wh.z, wh.w);
            unsigned long long v2 = interp_word(c00.z, c01.z, c10.z, c11.z, wh.x, wh.y, wh.z, wh.w);
            unsigned long long v3 = interp_word(c00.w, c01.w, c10.w, c11.w, wh.x, wh.y, wh.z, wh.w);
            s0 = add2(s0, v0); q0 = fma2(v0, v0, q0);
            s1 = add2(s1, v1); q1 = fma2(v1, v1, q1);
            s2 = add2(s2, v2); q2 = fma2(v2, v2, q2);
            s3 = add2(s3, v3); q3 = fma2(v3, v3, q3);
        }
        // finalize 8 channels
        float sa[8], qa[8];
        upk2(s0, sa[0], sa[1]); upk2(s1, sa[2], sa[3]);
        upk2(s2, sa[4], sa[5]); upk2(s3, sa[6], sa[7]);
        upk2(q0, qa[0], qa[1]); upk2(q1, qa[2], qa[3]);
        upk2(q2, qa[4], qa[5]); upk2(q3, qa[6], qa[7]);
        int sbase = (warp*32 + pt)*33 + cg*8;
        #pragma unroll
        for (int j = 0; j < 8; j++) {
            float m = sa[j] * invN;
            s_var[sbase + j] = qa[j]*invN - m*m;
        }
    }
    __syncthreads();

    // ---- planar write: g_var[c][g] ----
    int gg = gblock + tid;
    #pragma unroll
    for (int c = 0; c < CC; c++)
        g_var[(size_t)c*DHWSZ + gg] = s_var[tid*33 + c];
}

// ---------------- kernel 3: 3x3x3 conv, DT=6, 4 blocks/SM -------------------
__global__ void __launch_bounds__(CONV_THREADS, 4) k_conv(const float* __restrict__ wgt) {
    __shared__ float slab[HS][DS][WP];              // 6x8x168x4 = 32.3 KB
    __shared__ unsigned long long wpk[CPB*27];

    const int tid = threadIdx.x;
    const int h0  = blockIdx.x * HT;
    const int d0  = blockIdx.y * DT;
    const int c0  = blockIdx.z * CPB;
    float* __restrict__ outbuf = g_costp[blockIdx.z];
    const int wg  = tid % 40;
    const int hl  = tid / 40;
    const int w0  = wg * 4;

    for (int i = tid; i < CPB*27; i += CONV_THREADS) {
        float k = __ldg(wgt + c0*27 + i);
        wpk[i] = pk2(k, k);
    }
    for (int i = tid; i < HS*DS; i += CONV_THREADS) {
        int shy = i / DS, sdd = i % DS;
        float* row = &slab[shy][sdd][0];
        row[0] = 0.f; row[1] = 0.f; row[2] = 0.f; row[3] = 0.f;
        row[164] = 0.f; row[165] = 0.f; row[166] = 0.f; row[167] = 0.f;
    }

    unsigned long long A[DT][2];
    #pragma unroll
    for (int od = 0; od < DT; od++) { A[od][0] = 0ull; A[od][1] = 0ull; }

    #pragma unroll 1
    for (int c = 0; c < CPB; c++) {
        __syncthreads();

        // ---- cooperative slab load: 48 rows x 160 w = 1920 float4, 12 iters
        const float* __restrict__ vc = g_var + (size_t)(c0 + c) * DHWSZ;
        #pragma unroll
        for (int r = 0; r < 12; r++) {
            int idx = r*CONV_THREADS + tid;          // 0..1919
            int row = idx / 40;                      // 0..47
            int w4  = (idx % 40) * 4;
            int shy = row / DS;                      // 0..5
            int sdd = row - shy*DS;                  // 0..7
            int dd  = d0 - 1 + sdd;
            int hy  = h0 - 1 + shy;
            float4 v = make_float4(0.f, 0.f, 0.f, 0.f);
            if (dd >= 0 && dd < DDEP && hy >= 0 && hy < HH)
                v = *(const float4*)(vc + (size_t)dd*HWSZ + hy*WW + w4);
            *(float4*)&slab[shy][sdd][w4 + 4] = v;
        }
        __syncthreads();

        const unsigned long long* wc = wpk + c*27;
        #pragma unroll
        for (int dy = 0; dy < 3; dy++) {
            unsigned long long k00 = wc[(0*3+dy)*3+0], k01 = wc[(0*3+dy)*3+1], k02 = wc[(0*3+dy)*3+2];
            unsigned long long k10 = wc[(1*3+dy)*3+0], k11 = wc[(1*3+dy)*3+1], k12 = wc[(1*3+dy)*3+2];
            unsigned long long k20 = wc[(2*3+dy)*3+0], k21 = wc[(2*3+dy)*3+1], k22 = wc[(2*3+dy)*3+2];
            const float* hrow = &slab[hl + dy][0][0];
            #pragma unroll
            for (int sdd = 0; sdd < DS; sdd++) {
                const float* col = hrow + sdd*WP;
                float4 a = *(const float4*)(col + w0 + 4);
                float2 l = *(const float2*)(col + w0 + 2);
                float2 rr = *(const float2*)(col + w0 + 8);
                unsigned long long P0 = pk2(l.y,  a.x);
                unsigned long long P1 = pk2(a.x,  a.y);
                unsigned long long P2 = pk2(a.y,  a.z);
                unsigned long long P3 = pk2(a.z,  a.w);
                unsigned long long P4 = pk2(a.w,  rr.x);
                #pragma unroll
                for (int dz = 0; dz < 3; dz++) {
                    int od = sdd - dz;
                    if (od < 0 || od >= DT) continue;
                    unsigned long long q0 = (dz==0) ? k00 : (dz==1) ? k10 : k20;
                    unsigned long long q1 = (dz==0) ? k01 : (dz==1) ? k11 : k21;
                    unsigned long long q2 = (dz==0) ? k02 : (dz==1) ? k12 : k22;
                    A[od][0] = fma2(P0, q0, A[od][0]);
                    A[od][0] = fma2(P1, q1, A[od][0]);
                    A[od][0] = fma2(P2, q2, A[od][0]);
                    A[od][1] = fma2(P2, q0, A[od][1]);
                    A[od][1] = fma2(P3, q1, A[od][1]);
                    A[od][1] = fma2(P4, q2, A[od][1]);
                }
            }
        }
    }

    const int ob = (h0 + hl)*WW + w0;
    #pragma unroll
    for (int od = 0; od < DT; od++) {
        float o0, o1, o2, o3;
        upk2(A[od][0], o0, o1);
        upk2(A[od][1], o2, o3);
        float4 v = make_float4(o0, o1, o2, o3);
        *(float4*)(outbuf + (size_t)(d0 + od)*HWSZ + ob) = v;
    }
}

// ---------------- kernel 4: softmax / depth / confidence --------------------
__global__ void __launch_bounds__(128) k_post(const float* __restrict__ dv,
                                              float* __restrict__ out) {
    int pix = blockIdx.x * 128 + threadIdx.x;
    float p[DDEP];
    float mx = -1e30f;
    #pragma unroll
    for (int d = 0; d < DDEP; d++) {
        size_t o = (size_t)d*HWSZ + pix;
        p[d] = (g_costp[0][o] + g_costp[1][o]) + (g_costp[2][o] + g_costp[3][o]);
        mx = fmaxf(mx, p[d]);
    }
    float s = 0.0f;
    #pragma unroll
    for (int d = 0; d < DDEP; d++) { p[d] = expf(p[d] - mx); s += p[d]; }
    float inv = 1.0f / s;
    float depth = 0.0f, didx = 0.0f;
    #pragma unroll
    for (int d = 0; d < DDEP; d++) {
        float pr = p[d] * inv;
        p[d] = pr;
        depth += pr * __ldg(dv + d);
        didx  += pr * (float)d;
    }
    int di = (int)didx;
    di = min(max(di, 0), DDEP - 1);
    float conf = 0.0f;
    #pragma unroll
    for (int d = 0; d < DDEP; d++) {
        bool inwin = (d >= di - 1) && (d <= di + 2);
        conf += inwin ? p[d] : 0.0f;
    }
    out[pix]        = depth;
    out[HWSZ + pix] = conf;
}

// ---------------- launcher ---------------------------------------------------
extern "C" void kernel_launch(void* const* d_in, const int* in_sizes, int n_in,
                              void* d_out, int out_size) {
    const float* features = nullptr;
    const float* pm       = nullptr;
    const float* dv       = nullptr;
    const float* wgt      = nullptr;
    for (int i = 0; i < n_in; i++) {
        switch (in_sizes[i]) {
            case NV*CC*HWSZ: features = (const float*)d_in[i]; break;
            case 160:        pm       = (const float*)d_in[i]; break;
            case 48:         dv       = (const float*)d_in[i]; break;
            case 864:        wgt      = (const float*)d_in[i]; break;
            default: break;
        }
    }
    if (!features) features = (const float*)d_in[0];
    if (!pm)       pm       = (const float*)d_in[1];
    if (!dv)       dv       = (const float*)d_in[2];
    if (!wgt)      wgt      = (const float*)d_in[3];
    float* out = (float*)d_out;

    k_setup<<<1, 32>>>(pm);
    k_transpose<<<dim3(HWSZ/32, 1, NV), dim3(32, 32)>>>(features);
    k_var<<<DHWSZ/128, 128>>>(dv);
    k_conv<<<dim3(HH/HT, DDEP/DT, CSPLIT), CONV_THREADS>>>(wgt);
    k_post<<<HWSZ/128, 128>>>(dv, out);
}

// round 12
// speedup vs baseline: 1.2651x; 1.0367x over previous
#include <cuda_runtime.h>
#include <cuda_fp16.h>

#define NV 5
#define NS 4
#define CC 32
#define HH 128
#define WW 160
#define DDEP 48
#define HWSZ (HH*WW)          // 20480
#define DHWSZ (DDEP*HWSZ)     // 983040

// conv tiling
#define HT 4
#define HS 6
#define DT 6
#define DS 8
#define WP 168
#define CONV_THREADS 160
#define CSPLIT 4
#define CPB (CC/CSPLIT)       // 8 channels per block

// ---------------- scratch ----------------------------------------------------
__device__ float g_rot[NS][9];
__device__ float g_trans[NS][3];
__device__ __half g_feaH[NV*HWSZ*CC];           // (view, h, w, c) fp16, 6.5 MB
__device__ __half g_varH[(size_t)CC*DHWSZ];     // planar (c, d,h,w) fp16, 63 MB
__device__ float g_costp[CSPLIT][DHWSZ];        // partial costs

// ---------------- packed f32x2 helpers --------------------------------------
__device__ __forceinline__ unsigned long long pk2(float lo, float hi) {
    unsigned long long p;
    asm("mov.b64 %0, {%1, %2};" : "=l"(p) : "f"(lo), "f"(hi));
    return p;
}
__device__ __forceinline__ unsigned long long fma2(unsigned long long a,
                                                   unsigned long long b,
                                                   unsigned long long c) {
    unsigned long long d;
    asm("fma.rn.f32x2 %0, %1, %2, %3;" : "=l"(d) : "l"(a), "l"(b), "l"(c));
    return d;
}
__device__ __forceinline__ unsigned long long mul2(unsigned long long a,
                                                   unsigned long long b) {
    unsigned long long d;
    asm("mul.rn.f32x2 %0, %1, %2;" : "=l"(d) : "l"(a), "l"(b));
    return d;
}
__device__ __forceinline__ unsigned long long add2(unsigned long long a,
                                                   unsigned long long b) {
    unsigned long long d;
    asm("add.rn.f32x2 %0, %1, %2;" : "=l"(d) : "l"(a), "l"(b));
    return d;
}
__device__ __forceinline__ void upk2(unsigned long long p, float& lo, float& hi) {
    asm("mov.b64 {%0, %1}, %2;" : "=f"(lo), "=f"(hi) : "l"(p));
}
__device__ __forceinline__ __half2 u2h(unsigned int x) {
    return *reinterpret_cast<__half2*>(&x);
}
// fp16 bilinear for one half2 word; result as packed f32x2
__device__ __forceinline__ unsigned long long interp_word(
    unsigned int a00, unsigned int a01, unsigned int a10, unsigned int a11,
    unsigned int w0,  unsigned int w1,  unsigned int w2,  unsigned int w3)
{
    __half2 v = __hmul2(u2h(a11), u2h(w3));
    v = __hfma2(u2h(a10), u2h(w2), v);
    v = __hfma2(u2h(a01), u2h(w1), v);
    v = __hfma2(u2h(a00), u2h(w0), v);
    float2 f = __half22float2(v);
    return pk2(f.x, f.y);
}

// ---------------- kernel 0: projection setup (1 thread, fp32) ---------------
__global__ void k_setup(const float* __restrict__ pm) {
    if (threadIdx.x != 0 || blockIdx.x != 0) return;
    float fused[NV][16];
    for (int n = 0; n < NV; n++) {
        const float* p0 = pm + n * 32;
        const float* p1 = p0 + 16;
        for (int i = 0; i < 16; i++) fused[n][i] = p0[i];
        for (int i = 0; i < 3; i++)
            for (int j = 0; j < 4; j++) {
                float s = 0.0f;
                for (int k = 0; k < 3; k++) s += p1[i*4+k] * p0[k*4+j];
                fused[n][i*4+j] = s;
            }
    }
    float a[4][8];
    for (int i = 0; i < 4; i++)
        for (int j = 0; j < 4; j++) {
            a[i][j]   = fused[0][i*4+j];
            a[i][j+4] = (i == j) ? 1.0f : 0.0f;
        }
    for (int col = 0; col < 4; col++) {
        int piv = col;
        for (int r = col + 1; r < 4; r++)
            if (fabsf(a[r][col]) > fabsf(a[piv][col])) piv = r;
        if (piv != col)
            for (int j = 0; j < 8; j++) { float t = a[col][j]; a[col][j] = a[piv][j]; a[piv][j] = t; }
        float d = a[col][col];
        for (int j = 0; j < 8; j++) a[col][j] /= d;
        for (int r = 0; r < 4; r++) {
            if (r == col) continue;
            float f = a[r][col];
            for (int j = 0; j < 8; j++) a[r][j] -= f * a[col][j];
        }
    }
    float inv[16];
    for (int i = 0; i < 4; i++)
        for (int j = 0; j < 4; j++) inv[i*4+j] = a[i][j+4];

    for (int v = 1; v < NV; v++) {
        float P[16];
        for (int i = 0; i < 4; i++)
            for (int j = 0; j < 4; j++) {
                float s = 0.0f;
                for (int k = 0; k < 4; k++) s += fused[v][i*4+k] * inv[k*4+j];
                P[i*4+j] = s;
            }
        for (int i = 0; i < 3; i++)
            for (int j = 0; j < 3; j++) g_rot[v-1][i*3+j] = P[i*4+j];
        for (int i = 0; i < 3; i++) g_trans[v-1][i] = P[i*4+3];
    }
}

// ---------------- kernel 1: transpose (N,C,H,W) fp32 -> (N,HW,C) fp16 -------
__global__ void k_transpose(const float* __restrict__ f) {
    __shared__ float tile[32][33];
    int n  = blockIdx.z;
    int p0 = blockIdx.x * 32;
    int tx = threadIdx.x, ty = threadIdx.y;
    tile[ty][tx] = f[((size_t)(n*CC + ty))*HWSZ + p0 + tx];
    __syncthreads();
    g_feaH[((size_t)(n*HWSZ + p0 + ty))*CC + tx] = __float2half(tile[tx][ty]);
}

// ---------------- kernel 2: warp + variance, HFMA2 interp + f32x2 accum -----
__global__ void __launch_bounds__(128) k_var(const float* __restrict__ dv) {
    __shared__ int4  s_idx[4][4][32];
    __shared__ uint4 s_wth[4][4][32];   // {w,w} half2 x4 per (point, view)
    __shared__ int   s_hw [4][32];
    __shared__ float s_var[128*33];

    const int tid  = threadIdx.x;
    const int warp = tid >> 5;
    const int lane = tid & 31;
    const int gblock = blockIdx.x * 128;

    // ---- phase 1: per-thread projection descriptors for one point ----
    {
        int g  = gblock + tid;
        int d  = g / HWSZ;
        int hw = g - d * HWSZ;
        int h  = hw / WW;
        int w  = hw - h * WW;
        float fx = (float)w, fy = (float)h;
        float depth = __ldg(dv + d);
        #pragma unroll
        for (int v = 0; v < NS; v++) {
            float r0 = g_rot[v][0], r1 = g_rot[v][1], r2 = g_rot[v][2];
            float r3 = g_rot[v][3], r4 = g_rot[v][4], r5 = g_rot[v][5];
            float r6 = g_rot[v][6], r7 = g_rot[v][7], r8 = g_rot[v][8];
            float t0 = g_trans[v][0], t1 = g_trans[v][1], t2 = g_trans[v][2];
            float rx = r0*fx + r1*fy + r2;
            float ry = r3*fx + r4*fy + r5;
            float rz = r6*fx + r7*fy + r8;
            float X = rx*depth + t0;
            float Y = ry*depth + t1;
            float Z = rz*depth + t2;
            float px = __fdividef(X, Z);
            float py = __fdividef(Y, Z);
            float x0 = floorf(px), y0 = floorf(py);
            float x1 = x0 + 1.0f,  y1 = y0 + 1.0f;
            float wx1 = px - x0, wx0 = 1.0f - wx1;
            float wy1 = py - y0, wy0 = 1.0f - wy1;
            bool vx0 = (x0 >= 0.0f) && (x0 <= (float)(WW-1));
            bool vx1 = (x1 >= 0.0f) && (x1 <= (float)(WW-1));
            bool vy0 = (y0 >= 0.0f) && (y0 <= (float)(HH-1));
            bool vy1 = (y1 >= 0.0f) && (y1 <= (float)(HH-1));
            int cx0 = (int)fminf(fmaxf(x0, 0.0f), (float)(WW-1));
            int cx1 = (int)fminf(fmaxf(x1, 0.0f), (float)(WW-1));
            int cy0 = (int)fminf(fmaxf(y0, 0.0f), (float)(HH-1));
            int cy1 = (int)fminf(fmaxf(y1, 0.0f), (float)(HH-1));
            int4 id;
            id.x = cy0*WW + cx0;
            id.y = cy0*WW + cx1;
            id.z = cy1*WW + cx0;
            id.w = cy1*WW + cx1;
            float w00 = wx0*wy0 * ((vx0 && vy0) ? 1.0f : 0.0f);
            float w01 = wx1*wy0 * ((vx1 && vy0) ? 1.0f : 0.0f);
            float w10 = wx0*wy1 * ((vx0 && vy1) ? 1.0f : 0.0f);
            float w11 = wx1*wy1 * ((vx1 && vy1) ? 1.0f : 0.0f);
            __half2 h0 = __float2half2_rn(w00);
            __half2 h1 = __float2half2_rn(w01);
            __half2 h2 = __float2half2_rn(w10);
            __half2 h3 = __float2half2_rn(w11);
            uint4 wh;
            wh.x = *reinterpret_cast<unsigned int*>(&h0);
            wh.y = *reinterpret_cast<unsigned int*>(&h1);
            wh.z = *reinterpret_cast<unsigned int*>(&h2);
            wh.w = *reinterpret_cast<unsigned int*>(&h3);
            s_idx[warp][v][lane] = id;
            s_wth[warp][v][lane] = wh;
        }
        s_hw[warp][lane] = hw;
    }
    __syncwarp();

    // ---- phase 2: lanes = (cg 0..3 x q 0..7); 8 channels per thread --------
    const int cg = lane & 3;          // uint4 = 8 fp16 channels
    const int q  = lane >> 2;
    const uint4* fH4 = (const uint4*)g_feaH;   // pixel stride = 4 uint4
    const float invN = 1.0f / (float)NV;

    #pragma unroll
    for (int it = 0; it < 4; it++) {
        int pt  = it*8 + q;
        int hw2 = s_hw[warp][pt];
        uint4 rf = fH4[(size_t)hw2*4 + cg];
        unsigned long long s0, s1, s2, s3;
        {
            float2 f;
            f = __half22float2(u2h(rf.x)); s0 = pk2(f.x, f.y);
            f = __half22float2(u2h(rf.y)); s1 = pk2(f.x, f.y);
            f = __half22float2(u2h(rf.z)); s2 = pk2(f.x, f.y);
            f = __half22float2(u2h(rf.w)); s3 = pk2(f.x, f.y);
        }
        unsigned long long q0 = mul2(s0, s0);
        unsigned long long q1 = mul2(s1, s1);
        unsigned long long q2 = mul2(s2, s2);
        unsigned long long q3 = mul2(s3, s3);
        #pragma unroll
        for (int v = 0; v < NS; v++) {
            int4  id = s_idx[warp][v][pt];
            uint4 wh = s_wth[warp][v][pt];
            const uint4* fv = fH4 + (size_t)(v+1)*HWSZ*4;
            uint4 c00 = fv[(size_t)id.x*4 + cg];
            uint4 c01 = fv[(size_t)id.y*4 + cg];
            uint4 c10 = fv[(size_t)id.z*4 + cg];
            uint4 c11 = fv[(size_t)id.w*4 + cg];
            unsigned long long v0 = interp_word(c00.x, c01.x, c10.x, c11.x, wh.x, wh.y, wh.z, wh.w);
            unsigned long long v1 = interp_word(c00.y, c01.y, c10.y, c11.y, wh.x, wh.y, wh.z, wh.w);
            unsigned long long v2 = interp_word(c00.z, c01.z, c10.z, c11.z, wh.x, wh.y, wh.z, wh.w);
            unsigned long long v3 = interp_word(c00.w, c01.w, c10.w, c11.w, wh.x, wh.y, wh.z, wh.w);
            s0 = add2(s0, v0); q0 = fma2(v0, v0, q0);
            s1 = add2(s1, v1); q1 = fma2(v1, v1, q1);
            s2 = add2(s2, v2); q2 = fma2(v2, v2, q2);
            s3 = add2(s3, v3); q3 = fma2(v3, v3, q3);
        }
        // finalize 8 channels
        float sa[8], qa[8];
        upk2(s0, sa[0], sa[1]); upk2(s1, sa[2], sa[3]);
        upk2(s2, sa[4], sa[5]); upk2(s3, sa[6], sa[7]);
        upk2(q0, qa[0], qa[1]); upk2(q1, qa[2], qa[3]);
        upk2(q2, qa[4], qa[5]); upk2(q3, qa[6], qa[7]);
        int sbase = (warp*32 + pt)*33 + cg*8;
        #pragma unroll
        for (int j = 0; j < 8; j++) {
            float m = sa[j] * invN;
            s_var[sbase + j] = qa[j]*invN - m*m;
        }
    }
    __syncthreads();

    // ---- planar write (fp16): g_varH[c][g] ----
    int gg = gblock + tid;
    #pragma unroll
    for (int c = 0; c < CC; c++)
        g_varH[(size_t)c*DHWSZ + gg] = __float2half(s_var[tid*33 + c]);
}

// ---------------- kernel 3: 3x3x3 conv, fp16 gmem -> fp32 slab --------------
__global__ void __launch_bounds__(CONV_THREADS, 4) k_conv(const float* __restrict__ wgt) {
    __shared__ float slab[HS][DS][WP];              // 6x8x168x4 = 32.3 KB
    __shared__ unsigned long long wpk[CPB*27];

    const int tid = threadIdx.x;
    const int h0  = blockIdx.x * HT;
    const int d0  = blockIdx.y * DT;
    const int c0  = blockIdx.z * CPB;
    float* __restrict__ outbuf = g_costp[blockIdx.z];
    const int wg  = tid % 40;
    const int hl  = tid / 40;
    const int w0  = wg * 4;

    for (int i = tid; i < CPB*27; i += CONV_THREADS) {
        float k = __ldg(wgt + c0*27 + i);
        wpk[i] = pk2(k, k);
    }
    for (int i = tid; i < HS*DS; i += CONV_THREADS) {
        int shy = i / DS, sdd = i % DS;
        float* row = &slab[shy][sdd][0];
        row[0] = 0.f; row[1] = 0.f; row[2] = 0.f; row[3] = 0.f;
        row[164] = 0.f; row[165] = 0.f; row[166] = 0.f; row[167] = 0.f;
    }

    unsigned long long A[DT][2];
    #pragma unroll
    for (int od = 0; od < DT; od++) { A[od][0] = 0ull; A[od][1] = 0ull; }

    #pragma unroll 1
    for (int c = 0; c < CPB; c++) {
        __syncthreads();

        // ---- cooperative slab load: 48 rows x 20 uint4 (8 halves) = 960 ----
        const __half* __restrict__ vc = g_varH + (size_t)(c0 + c) * DHWSZ;
        #pragma unroll
        for (int r = 0; r < 6; r++) {
            int idx = r*CONV_THREADS + tid;          // 0..959
            int row = idx / 20;                      // 0..47
            int w8  = (idx % 20) * 8;
            int shy = row / DS;                      // 0..5
            int sdd = row - shy*DS;                  // 0..7
            int dd  = d0 - 1 + sdd;
            int hy  = h0 - 1 + shy;
            uint4 v = make_uint4(0u, 0u, 0u, 0u);
            if (dd >= 0 && dd < DDEP && hy >= 0 && hy < HH)
                v = *(const uint4*)(vc + (size_t)dd*HWSZ + hy*WW + w8);
            float2 f0 = __half22float2(u2h(v.x));
            float2 f1 = __half22float2(u2h(v.y));
            float2 f2 = __half22float2(u2h(v.z));
            float2 f3 = __half22float2(u2h(v.w));
            float* dst = &slab[shy][sdd][w8 + 4];
            *(float4*)(dst)     = make_float4(f0.x, f0.y, f1.x, f1.y);
            *(float4*)(dst + 4) = make_float4(f2.x, f2.y, f3.x, f3.y);
        }
        __syncthreads();

        const unsigned long long* wc = wpk + c*27;
        #pragma unroll
        for (int dy = 0; dy < 3; dy++) {
            unsigned long long k00 = wc[(0*3+dy)*3+0], k01 = wc[(0*3+dy)*3+1], k02 = wc[(0*3+dy)*3+2];
            unsigned long long k10 = wc[(1*3+dy)*3+0], k11 = wc[(1*3+dy)*3+1], k12 = wc[(1*3+dy)*3+2];
            unsigned long long k20 = wc[(2*3+dy)*3+0], k21 = wc[(2*3+dy)*3+1], k22 = wc[(2*3+dy)*3+2];
            const float* hrow = &slab[hl + dy][0][0];
            #pragma unroll
            for (int sdd = 0; sdd < DS; sdd++) {
                const float* col = hrow + sdd*WP;
                float4 a = *(const float4*)(col + w0 + 4);
                float2 l = *(const float2*)(col + w0 + 2);
                float2 rr = *(const float2*)(col + w0 + 8);
                unsigned long long P0 = pk2(l.y,  a.x);
                unsigned long long P1 = pk2(a.x,  a.y);
                unsigned long long P2 = pk2(a.y,  a.z);
                unsigned long long P3 = pk2(a.z,  a.w);
                unsigned long long P4 = pk2(a.w,  rr.x);
                #pragma unroll
                for (int dz = 0; dz < 3; dz++) {
                    int od = sdd - dz;
                    if (od < 0 || od >= DT) continue;
                    unsigned long long q0 = (dz==0) ? k00 : (dz==1) ? k10 : k20;
                    unsigned long long q1 = (dz==0) ? k01 : (dz==1) ? k11 : k21;
                    unsigned long long q2 = (dz==0) ? k02 : (dz==1) ? k12 : k22;
                    A[od][0] = fma2(P0, q0, A[od][0]);
                    A[od][0] = fma2(P1, q1, A[od][0]);
                    A[od][0] = fma2(P2, q2, A[od][0]);
                    A[od][1] = fma2(P2, q0, A[od][1]);
                    A[od][1] = fma2(P3, q1, A[od][1]);
                    A[od][1] = fma2(P4, q2, A[od][1]);
                }
            }
        }
    }

    const int ob = (h0 + hl)*WW + w0;
    #pragma unroll
    for (int od = 0; od < DT; od++) {
        float o0, o1, o2, o3;
        upk2(A[od][0], o0, o1);
        upk2(A[od][1], o2, o3);
        float4 v = make_float4(o0, o1, o2, o3);
        *(float4*)(outbuf + (size_t)(d0 + od)*HWSZ + ob) = v;
    }
}

// ---------------- kernel 4: softmax / depth / confidence --------------------
__global__ void __launch_bounds__(128) k_post(const float* __restrict__ dv,
                                              float* __restrict__ out) {
    int pix = blockIdx.x * 128 + threadIdx.x;
    float p[DDEP];
    float mx = -1e30f;
    #pragma unroll
    for (int d = 0; d < DDEP; d++) {
        size_t o = (size_t)d*HWSZ + pix;
        p[d] = (g_costp[0][o] + g_costp[1][o]) + (g_costp[2][o] + g_costp[3][o]);
        mx = fmaxf(mx, p[d]);
    }
    float s = 0.0f;
    #pragma unroll
    for (int d = 0; d < DDEP; d++) { p[d] = expf(p[d] - mx); s += p[d]; }
    float inv = 1.0f / s;
    float depth = 0.0f, didx = 0.0f;
    #pragma unroll
    for (int d = 0; d < DDEP; d++) {
        float pr = p[d] * inv;
        p[d] = pr;
        depth += pr * __ldg(dv + d);
        didx  += pr * (float)d;
    }
    int di = (int)didx;
    di = min(max(di, 0), DDEP - 1);
    float conf = 0.0f;
    #pragma unroll
    for (int d = 0; d < DDEP; d++) {
        bool inwin = (d >= di - 1) && (d <= di + 2);
        conf += inwin ? p[d] : 0.0f;
    }
    out[pix]        = depth;
    out[HWSZ + pix] = conf;
}

// ---------------- launcher ---------------------------------------------------
extern "C" void kernel_launch(void* const* d_in, const int* in_sizes, int n_in,
                              void* d_out, int out_size) {
    const float* features = nullptr;
    const float* pm       = nullptr;
    const float* dv       = nullptr;
    const float* wgt      = nullptr;
    for (int i = 0; i < n_in; i++) {
        switch (in_sizes[i]) {
            case NV*CC*HWSZ: features = (const float*)d_in[i]; break;
            case 160:        pm       = (const float*)d_in[i]; break;
            case 48:         dv       = (const float*)d_in[i]; break;
            case 864:        wgt      = (const float*)d_in[i]; break;
            default: break;
        }
    }
    if (!features) features = (const float*)d_in[0];
    if (!pm)       pm       = (const float*)d_in[1];
    if (!dv)       dv       = (const float*)d_in[2];
    if (!wgt)      wgt      = (const float*)d_in[3];
    float* out = (float*)d_out;

    k_setup<<<1, 32>>>(pm);
    k_transpose<<<dim3(HWSZ/32, 1, NV), dim3(32, 32)>>>(features);
    k_var<<<DHWSZ/128, 128>>>(dv);
    k_conv<<<dim3(HH/HT, DDEP/DT, CSPLIT), CONV_THREADS>>>(wgt);
    k_post<<<HWSZ/128, 128>>>(dv, out);
}

// round 13
// speedup vs baseline: 1.3127x; 1.0377x over previous
#include <cuda_runtime.h>
#include <cuda_fp16.h>

#define NV 5
#define NS 4
#define CC 32
#define HH 128
#define WW 160
#define DDEP 48
#define HWSZ (HH*WW)          // 20480
#define DHWSZ (DDEP*HWSZ)     // 983040

// conv tiling
#define HT 4
#define HS 6
#define DT 6
#define DS 8
#define WPH 168               // halves per slab row: 2 halo + 160 + 6 pad
#define CONV_THREADS 160
#define CSPLIT 4
#define CPB (CC/CSPLIT)       // 8 channels per block

// ---------------- scratch ----------------------------------------------------
__device__ float g_rot[NS][9];
__device__ float g_trans[NS][3];
__device__ __half g_feaH[NV*HWSZ*CC];           // (view, h, w, c) fp16, 6.5 MB
__device__ __half g_varH[(size_t)CC*DHWSZ];     // planar (c, d,h,w) fp16, 63 MB
__device__ float g_costp[CSPLIT][DHWSZ];        // partial costs

// ---------------- packed f32x2 helpers --------------------------------------
__device__ __forceinline__ unsigned long long pk2(float lo, float hi) {
    unsigned long long p;
    asm("mov.b64 %0, {%1, %2};" : "=l"(p) : "f"(lo), "f"(hi));
    return p;
}
__device__ __forceinline__ unsigned long long fma2(unsigned long long a,
                                                   unsigned long long b,
                                                   unsigned long long c) {
    unsigned long long d;
    asm("fma.rn.f32x2 %0, %1, %2, %3;" : "=l"(d) : "l"(a), "l"(b), "l"(c));
    return d;
}
__device__ __forceinline__ unsigned long long mul2(unsigned long long a,
                                                   unsigned long long b) {
    unsigned long long d;
    asm("mul.rn.f32x2 %0, %1, %2;" : "=l"(d) : "l"(a), "l"(b));
    return d;
}
__device__ __forceinline__ unsigned long long add2(unsigned long long a,
                                                   unsigned long long b) {
    unsigned long long d;
    asm("add.rn.f32x2 %0, %1, %2;" : "=l"(d) : "l"(a), "l"(b));
    return d;
}
__device__ __forceinline__ void upk2(unsigned long long p, float& lo, float& hi) {
    asm("mov.b64 {%0, %1}, %2;" : "=f"(lo), "=f"(hi) : "l"(p));
}
__device__ __forceinline__ __half2 u2h(unsigned int x) {
    return *reinterpret_cast<__half2*>(&x);
}
// fp16 bilinear for one half2 word; result as packed f32x2
__device__ __forceinline__ unsigned long long interp_word(
    unsigned int a00, unsigned int a01, unsigned int a10, unsigned int a11,
    unsigned int w0,  unsigned int w1,  unsigned int w2,  unsigned int w3)
{
    __half2 v = __hmul2(u2h(a11), u2h(w3));
    v = __hfma2(u2h(a10), u2h(w2), v);
    v = __hfma2(u2h(a01), u2h(w1), v);
    v = __hfma2(u2h(a00), u2h(w0), v);
    float2 f = __half22float2(v);
    return pk2(f.x, f.y);
}

// ---------------- kernel 0: projection setup (1 thread, fp32) ---------------
__global__ void k_setup(const float* __restrict__ pm) {
    if (threadIdx.x != 0 || blockIdx.x != 0) return;
    float fused[NV][16];
    for (int n = 0; n < NV; n++) {
        const float* p0 = pm + n * 32;
        const float* p1 = p0 + 16;
        for (int i = 0; i < 16; i++) fused[n][i] = p0[i];
        for (int i = 0; i < 3; i++)
            for (int j = 0; j < 4; j++) {
                float s = 0.0f;
                for (int k = 0; k < 3; k++) s += p1[i*4+k] * p0[k*4+j];
                fused[n][i*4+j] = s;
            }
    }
    float a[4][8];
    for (int i = 0; i < 4; i++)
        for (int j = 0; j < 4; j++) {
            a[i][j]   = fused[0][i*4+j];
            a[i][j+4] = (i == j) ? 1.0f : 0.0f;
        }
    for (int col = 0; col < 4; col++) {
        int piv = col;
        for (int r = col + 1; r < 4; r++)
            if (fabsf(a[r][col]) > fabsf(a[piv][col])) piv = r;
        if (piv != col)
            for (int j = 0; j < 8; j++) { float t = a[col][j]; a[col][j] = a[piv][j]; a[piv][j] = t; }
        float d = a[col][col];
        for (int j = 0; j < 8; j++) a[col][j] /= d;
        for (int r = 0; r < 4; r++) {
            if (r == col) continue;
            float f = a[r][col];
            for (int j = 0; j < 8; j++) a[r][j] -= f * a[col][j];
        }
    }
    float inv[16];
    for (int i = 0; i < 4; i++)
        for (int j = 0; j < 4; j++) inv[i*4+j] = a[i][j+4];

    for (int v = 1; v < NV; v++) {
        float P[16];
        for (int i = 0; i < 4; i++)
            for (int j = 0; j < 4; j++) {
                float s = 0.0f;
                for (int k = 0; k < 4; k++) s += fused[v][i*4+k] * inv[k*4+j];
                P[i*4+j] = s;
            }
        for (int i = 0; i < 3; i++)
            for (int j = 0; j < 3; j++) g_rot[v-1][i*3+j] = P[i*4+j];
        for (int i = 0; i < 3; i++) g_trans[v-1][i] = P[i*4+3];
    }
}

// ---------------- kernel 1: transpose (N,C,H,W) fp32 -> (N,HW,C) fp16 -------
__global__ void k_transpose(const float* __restrict__ f) {
    __shared__ float tile[32][33];
    int n  = blockIdx.z;
    int p0 = blockIdx.x * 32;
    int tx = threadIdx.x, ty = threadIdx.y;
    tile[ty][tx] = f[((size_t)(n*CC + ty))*HWSZ + p0 + tx];
    __syncthreads();
    g_feaH[((size_t)(n*HWSZ + p0 + ty))*CC + tx] = __float2half(tile[tx][ty]);
}

// ---------------- kernel 2: warp + variance, HFMA2 interp + f32x2 accum -----
__global__ void __launch_bounds__(128) k_var(const float* __restrict__ dv) {
    __shared__ int4  s_idx[4][4][32];
    __shared__ uint4 s_wth[4][4][32];   // {w,w} half2 x4 per (point, view)
    __shared__ int   s_hw [4][32];
    __shared__ float s_var[128*33];

    const int tid  = threadIdx.x;
    const int warp = tid >> 5;
    const int lane = tid & 31;
    const int gblock = blockIdx.x * 128;

    // ---- phase 1: per-thread projection descriptors for one point ----
    {
        int g  = gblock + tid;
        int d  = g / HWSZ;
        int hw = g - d * HWSZ;
        int h  = hw / WW;
        int w  = hw - h * WW;
        float fx = (float)w, fy = (float)h;
        float depth = __ldg(dv + d);
        #pragma unroll
        for (int v = 0; v < NS; v++) {
            float r0 = g_rot[v][0], r1 = g_rot[v][1], r2 = g_rot[v][2];
            float r3 = g_rot[v][3], r4 = g_rot[v][4], r5 = g_rot[v][5];
            float r6 = g_rot[v][6], r7 = g_rot[v][7], r8 = g_rot[v][8];
            float t0 = g_trans[v][0], t1 = g_trans[v][1], t2 = g_trans[v][2];
            float rx = r0*fx + r1*fy + r2;
            float ry = r3*fx + r4*fy + r5;
            float rz = r6*fx + r7*fy + r8;
            float X = rx*depth + t0;
            float Y = ry*depth + t1;
            float Z = rz*depth + t2;
            float px = __fdividef(X, Z);
            float py = __fdividef(Y, Z);
            float x0 = floorf(px), y0 = floorf(py);
            float x1 = x0 + 1.0f,  y1 = y0 + 1.0f;
            float wx1 = px - x0, wx0 = 1.0f - wx1;
            float wy1 = py - y0, wy0 = 1.0f - wy1;
            bool vx0 = (x0 >= 0.0f) && (x0 <= (float)(WW-1));
            bool vx1 = (x1 >= 0.0f) && (x1 <= (float)(WW-1));
            bool vy0 = (y0 >= 0.0f) && (y0 <= (float)(HH-1));
            bool vy1 = (y1 >= 0.0f) && (y1 <= (float)(HH-1));
            int cx0 = (int)fminf(fmaxf(x0, 0.0f), (float)(WW-1));
            int cx1 = (int)fminf(fmaxf(x1, 0.0f), (float)(WW-1));
            int cy0 = (int)fminf(fmaxf(y0, 0.0f), (float)(HH-1));
            int cy1 = (int)fminf(fmaxf(y1, 0.0f), (float)(HH-1));
            int4 id;
            id.x = cy0*WW + cx0;
            id.y = cy0*WW + cx1;
            id.z = cy1*WW + cx0;
            id.w = cy1*WW + cx1;
            float w00 = wx0*wy0 * ((vx0 && vy0) ? 1.0f : 0.0f);
            float w01 = wx1*wy0 * ((vx1 && vy0) ? 1.0f : 0.0f);
            float w10 = wx0*wy1 * ((vx0 && vy1) ? 1.0f : 0.0f);
            float w11 = wx1*wy1 * ((vx1 && vy1) ? 1.0f : 0.0f);
            __half2 h0 = __float2half2_rn(w00);
            __half2 h1 = __float2half2_rn(w01);
            __half2 h2 = __float2half2_rn(w10);
            __half2 h3 = __float2half2_rn(w11);
            uint4 wh;
            wh.x = *reinterpret_cast<unsigned int*>(&h0);
            wh.y = *reinterpret_cast<unsigned int*>(&h1);
            wh.z = *reinterpret_cast<unsigned int*>(&h2);
            wh.w = *reinterpret_cast<unsigned int*>(&h3);
            s_idx[warp][v][lane] = id;
            s_wth[warp][v][lane] = wh;
        }
        s_hw[warp][lane] = hw;
    }
    __syncwarp();

    // ---- phase 2: lanes = (cg 0..3 x q 0..7); 8 channels per thread --------
    const int cg = lane & 3;          // uint4 = 8 fp16 channels
    const int q  = lane >> 2;
    const uint4* fH4 = (const uint4*)g_feaH;   // pixel stride = 4 uint4
    const float invN = 1.0f / (float)NV;

    #pragma unroll
    for (int it = 0; it < 4; it++) {
        int pt  = it*8 + q;
        int hw2 = s_hw[warp][pt];
        uint4 rf = fH4[(size_t)hw2*4 + cg];
        unsigned long long s0, s1, s2, s3;
        {
            float2 f;
            f = __half22float2(u2h(rf.x)); s0 = pk2(f.x, f.y);
            f = __half22float2(u2h(rf.y)); s1 = pk2(f.x, f.y);
            f = __half22float2(u2h(rf.z)); s2 = pk2(f.x, f.y);
            f = __half22float2(u2h(rf.w)); s3 = pk2(f.x, f.y);
        }
        unsigned long long q0 = mul2(s0, s0);
        unsigned long long q1 = mul2(s1, s1);
        unsigned long long q2 = mul2(s2, s2);
        unsigned long long q3 = mul2(s3, s3);
        #pragma unroll
        for (int v = 0; v < NS; v++) {
            int4  id = s_idx[warp][v][pt];
            uint4 wh = s_wth[warp][v][pt];
            const uint4* fv = fH4 + (size_t)(v+1)*HWSZ*4;
            uint4 c00 = fv[(size_t)id.x*4 + cg];
            uint4 c01 = fv[(size_t)id.y*4 + cg];
            uint4 c10 = fv[(size_t)id.z*4 + cg];
            uint4 c11 = fv[(size_t)id.w*4 + cg];
            unsigned long long v0 = interp_word(c00.x, c01.x, c10.x, c11.x, wh.x, wh.y, wh.z, wh.w);
            unsigned long long v1 = interp_word(c00.y, c01.y, c10.y, c11.y, wh.x, wh.y, wh.z, wh.w);
            unsigned long long v2 = interp_word(c00.z, c01.z, c10.z, c11.z, wh.x, wh.y, wh.z, wh.w);
            unsigned long long v3 = interp_word(c00.w, c01.w, c10.w, c11.w, wh.x, wh.y, wh.z, wh.w);
            s0 = add2(s0, v0); q0 = fma2(v0, v0, q0);
            s1 = add2(s1, v1); q1 = fma2(v1, v1, q1);
            s2 = add2(s2, v2); q2 = fma2(v2, v2, q2);
            s3 = add2(s3, v3); q3 = fma2(v3, v3, q3);
        }
        // finalize 8 channels
        float sa[8], qa[8];
        upk2(s0, sa[0], sa[1]); upk2(s1, sa[2], sa[3]);
        upk2(s2, sa[4], sa[5]); upk2(s3, sa[6], sa[7]);
        upk2(q0, qa[0], qa[1]); upk2(q1, qa[2], qa[3]);
        upk2(q2, qa[4], qa[5]); upk2(q3, qa[6], qa[7]);
        int sbase = (warp*32 + pt)*33 + cg*8;
        #pragma unroll
        for (int j = 0; j < 8; j++) {
            float m = sa[j] * invN;
            s_var[sbase + j] = qa[j]*invN - m*m;
        }
    }
    __syncthreads();

    // ---- planar write (fp16, pixel-pair packed): g_varH[c][gblock + 2p..] --
    {
        const int p  = (tid & 63) * 2;        // pixel pair within block
        const int cb = (tid >> 6) * 16;       // channel half
        const size_t gb = (size_t)gblock + p;
        #pragma unroll
        for (int j = 0; j < 16; j++) {
            int c = cb + j;
            __half2 hv = __floats2half2_rn(s_var[p*33 + c], s_var[(p+1)*33 + c]);
            *reinterpret_cast<unsigned int*>(g_varH + (size_t)c*DHWSZ + gb) =
                *reinterpret_cast<unsigned int*>(&hv);
        }
    }
}

// ---------------- kernel 3: 3x3x3 conv, fp16 slab (numerics-identical) ------
__global__ void __launch_bounds__(CONV_THREADS, 4) k_conv(const float* __restrict__ wgt) {
    __shared__ __half slabH[HS][DS][WPH];           // 16.1 KB
    __shared__ unsigned long long wpk[CPB*27];

    const int tid = threadIdx.x;
    const int h0  = blockIdx.x * HT;
    const int d0  = blockIdx.y * DT;
    const int c0  = blockIdx.z * CPB;
    float* __restrict__ outbuf = g_costp[blockIdx.z];
    const int wg  = tid % 40;
    const int hl  = tid / 40;
    const int w0  = wg * 4;

    for (int i = tid; i < CPB*27; i += CONV_THREADS) {
        float k = __ldg(wgt + c0*27 + i);
        wpk[i] = pk2(k, k);
    }
    // zero halo: halves [0,2) and [162,168) of every row
    for (int i = tid; i < HS*DS; i += CONV_THREADS) {
        int shy = i / DS, sdd = i % DS;
        __half* row = &slabH[shy][sdd][0];
        *reinterpret_cast<unsigned int*>(row)       = 0u;          // halves 0,1
        *reinterpret_cast<unsigned int*>(row + 162) = 0u;          // 162,163
        *reinterpret_cast<unsigned int*>(row + 164) = 0u;          // 164,165
        *reinterpret_cast<unsigned int*>(row + 166) = 0u;          // 166,167
    }

    unsigned long long A[DT][2];
    #pragma unroll
    for (int od = 0; od < DT; od++) { A[od][0] = 0ull; A[od][1] = 0ull; }

    #pragma unroll 1
    for (int c = 0; c < CPB; c++) {
        __syncthreads();

        // ---- cooperative slab copy: 48 rows x 20 uint4 (8 halves) = 960 ----
        const __half* __restrict__ vc = g_varH + (size_t)(c0 + c) * DHWSZ;
        #pragma unroll
        for (int r = 0; r < 6; r++) {
            int idx = r*CONV_THREADS + tid;          // 0..959
            int row = idx / 20;                      // 0..47
            int w8  = (idx % 20) * 8;
            int shy = row / DS;                      // 0..5
            int sdd = row - shy*DS;                  // 0..7
            int dd  = d0 - 1 + sdd;
            int hy  = h0 - 1 + shy;
            uint4 v = make_uint4(0u, 0u, 0u, 0u);
            if (dd >= 0 && dd < DDEP && hy >= 0 && hy < HH)
                v = *(const uint4*)(vc + (size_t)dd*HWSZ + hy*WW + w8);
            unsigned int* dst = reinterpret_cast<unsigned int*>(&slabH[shy][sdd][2 + w8]);
            dst[0] = v.x; dst[1] = v.y; dst[2] = v.z; dst[3] = v.w;
        }
        __syncthreads();

        const unsigned long long* wc = wpk + c*27;
        #pragma unroll
        for (int dy = 0; dy < 3; dy++) {
            unsigned long long k00 = wc[(0*3+dy)*3+0], k01 = wc[(0*3+dy)*3+1], k02 = wc[(0*3+dy)*3+2];
            unsigned long long k10 = wc[(1*3+dy)*3+0], k11 = wc[(1*3+dy)*3+1], k12 = wc[(1*3+dy)*3+2];
            unsigned long long k20 = wc[(2*3+dy)*3+0], k21 = wc[(2*3+dy)*3+1], k22 = wc[(2*3+dy)*3+2];
            const __half* hrow = &slabH[hl + dy][0][0];
            #pragma unroll
            for (int sdd = 0; sdd < DS; sdd++) {
                const __half* col = hrow + sdd*WPH;
                // halves at index (2 + w0 + j) hold value v_j; reads 8B-aligned
                uint2 u0 = *(const uint2*)(col + w0);       // (v-2,v-1),(v0,v1)
                uint2 u1 = *(const uint2*)(col + w0 + 4);   // (v2,v3),(v4,v5)
                float2 fA = __half22float2(u2h(u0.x));
                float2 fB = __half22float2(u2h(u0.y));
                float2 fC = __half22float2(u2h(u1.x));
                float2 fD = __half22float2(u2h(u1.y));
                unsigned long long P0 = pk2(fA.y, fB.x);    // (v-1,v0)
                unsigned long long P1 = pk2(fB.x, fB.y);    // (v0,v1)
                unsigned long long P2 = pk2(fB.y, fC.x);    // (v1,v2)
                unsigned long long P3 = pk2(fC.x, fC.y);    // (v2,v3)
                unsigned long long P4 = pk2(fC.y, fD.x);    // (v3,v4)
                #pragma unroll
                for (int dz = 0; dz < 3; dz++) {
                    int od = sdd - dz;
                    if (od < 0 || od >= DT) continue;
                    unsigned long long q0 = (dz==0) ? k00 : (dz==1) ? k10 : k20;
                    unsigned long long q1 = (dz==0) ? k01 : (dz==1) ? k11 : k21;
                    unsigned long long q2 = (dz==0) ? k02 : (dz==1) ? k12 : k22;
                    A[od][0] = fma2(P0, q0, A[od][0]);
                    A[od][0] = fma2(P1, q1, A[od][0]);
                    A[od][0] = fma2(P2, q2, A[od][0]);
                    A[od][1] = fma2(P2, q0, A[od][1]);
                    A[od][1] = fma2(P3, q1, A[od][1]);
                    A[od][1] = fma2(P4, q2, A[od][1]);
                }
            }
        }
    }

    const int ob = (h0 + hl)*WW + w0;
    #pragma unroll
    for (int od = 0; od < DT; od++) {
        float o0, o1, o2, o3;
        upk2(A[od][0], o0, o1);
        upk2(A[od][1], o2, o3);
        float4 v = make_float4(o0, o1, o2, o3);
        *(float4*)(outbuf + (size_t)(d0 + od)*HWSZ + ob) = v;
    }
}

// ---------------- kernel 4: softmax / depth / confidence --------------------
__global__ void __launch_bounds__(128) k_post(const float* __restrict__ dv,
                                              float* __restrict__ out) {
    int pix = blockIdx.x * 128 + threadIdx.x;
    float p[DDEP];
    float mx = -1e30f;
    #pragma unroll
    for (int d = 0; d < DDEP; d++) {
        size_t o = (size_t)d*HWSZ + pix;
        p[d] = (g_costp[0][o] + g_costp[1][o]) + (g_costp[2][o] + g_costp[3][o]);
        mx = fmaxf(mx, p[d]);
    }
    float s = 0.0f;
    #pragma unroll
    for (int d = 0; d < DDEP; d++) { p[d] = expf(p[d] - mx); s += p[d]; }
    float inv = 1.0f / s;
    float depth = 0.0f, didx = 0.0f;
    #pragma unroll
    for (int d = 0; d < DDEP; d++) {
        float pr = p[d] * inv;
        p[d] = pr;
        depth += pr * __ldg(dv + d);
        didx  += pr * (float)d;
    }
    int di = (int)didx;
    di = min(max(di, 0), DDEP - 1);
    float conf = 0.0f;
    #pragma unroll
    for (int d = 0; d < DDEP; d++) {
        bool inwin = (d >= di - 1) && (d <= di + 2);
        conf += inwin ? p[d] : 0.0f;
    }
    out[pix]        = depth;
    out[HWSZ + pix] = conf;
}

// ---------------- launcher ---------------------------------------------------
extern "C" void kernel_launch(void* const* d_in, const int* in_sizes, int n_in,
                              void* d_out, int out_size) {
    const float* features = nullptr;
    const float* pm       = nullptr;
    const float* dv       = nullptr;
    const float* wgt      = nullptr;
    for (int i = 0; i < n_in; i++) {
        switch (in_sizes[i]) {
            case NV*CC*HWSZ: features = (const float*)d_in[i]; break;
            case 160:        pm       = (const float*)d_in[i]; break;
            case 48:         dv       = (const float*)d_in[i]; break;
            case 864:        wgt      = (const float*)d_in[i]; break;
            default: break;
        }
    }
    if (!features) features = (const float*)d_in[0];
    if (!pm)       pm       = (const float*)d_in[1];
    if (!dv)       dv       = (const float*)d_in[2];
    if (!wgt)      wgt      = (const float*)d_in[3];
    float* out = (float*)d_out;

    k_setup<<<1, 32>>>(pm);
    k_transpose<<<dim3(HWSZ/32, 1, NV), dim3(32, 32)>>>(features);
    k_var<<<DHWSZ/128, 128>>>(dv);
    k_conv<<<dim3(HH/HT, DDEP/DT, CSPLIT), CONV_THREADS>>>(wgt);
    k_post<<<HWSZ/128, 128>>>(dv, out);
}

// round 14
// speedup vs baseline: 1.3163x; 1.0028x over previous
#include <cuda_runtime.h>
#include <cuda_fp16.h>

#define NV 5
#define NS 4
#define CC 32
#define HH 128
#define WW 160
#define DDEP 48
#define HWSZ (HH*WW)          // 20480
#define DHWSZ (DDEP*HWSZ)     // 983040

// conv tiling
#define HT 4
#define HS 6
#define DT 6
#define DS 8
#define WPH 168               // halves per slab row: 2 halo + 160 + 6 pad
#define CONV_THREADS 160
#define CSPLIT 4
#define CPB (CC/CSPLIT)       // 8 channels per block

// ---------------- scratch ----------------------------------------------------
__device__ float g_rot[NS][9];
__device__ float g_trans[NS][3];
__device__ __half g_feaH[NV*HWSZ*CC];           // (view, h, w, c) fp16, 6.5 MB
__device__ __half g_varH[(size_t)CC*DHWSZ];     // planar (c, d,h,w) fp16, 63 MB
__device__ float g_costp[CSPLIT][DHWSZ];        // partial costs

// ---------------- packed f32x2 helpers --------------------------------------
__device__ __forceinline__ unsigned long long pk2(float lo, float hi) {
    unsigned long long p;
    asm("mov.b64 %0, {%1, %2};" : "=l"(p) : "f"(lo), "f"(hi));
    return p;
}
__device__ __forceinline__ unsigned long long fma2(unsigned long long a,
                                                   unsigned long long b,
                                                   unsigned long long c) {
    unsigned long long d;
    asm("fma.rn.f32x2 %0, %1, %2, %3;" : "=l"(d) : "l"(a), "l"(b), "l"(c));
    return d;
}
__device__ __forceinline__ unsigned long long mul2(unsigned long long a,
                                                   unsigned long long b) {
    unsigned long long d;
    asm("mul.rn.f32x2 %0, %1, %2;" : "=l"(d) : "l"(a), "l"(b));
    return d;
}
__device__ __forceinline__ unsigned long long add2(unsigned long long a,
                                                   unsigned long long b) {
    unsigned long long d;
    asm("add.rn.f32x2 %0, %1, %2;" : "=l"(d) : "l"(a), "l"(b));
    return d;
}
__device__ __forceinline__ void upk2(unsigned long long p, float& lo, float& hi) {
    asm("mov.b64 {%0, %1}, %2;" : "=f"(lo), "=f"(hi) : "l"(p));
}
__device__ __forceinline__ __half2 u2h(unsigned int x) {
    return *reinterpret_cast<__half2*>(&x);
}
// fp16 bilinear for one half2 word; result as packed f32x2
__device__ __forceinline__ unsigned long long interp_word(
    unsigned int a00, unsigned int a01, unsigned int a10, unsigned int a11,
    unsigned int w0,  unsigned int w1,  unsigned int w2,  unsigned int w3)
{
    __half2 v = __hmul2(u2h(a11), u2h(w3));
    v = __hfma2(u2h(a10), u2h(w2), v);
    v = __hfma2(u2h(a01), u2h(w1), v);
    v = __hfma2(u2h(a00), u2h(w0), v);
    float2 f = __half22float2(v);
    return pk2(f.x, f.y);
}

// ---------------- kernel 0: projection setup (1 thread, fp32) ---------------
__global__ void k_setup(const float* __restrict__ pm) {
    if (threadIdx.x != 0 || blockIdx.x != 0) return;
    float fused[NV][16];
    for (int n = 0; n < NV; n++) {
        const float* p0 = pm + n * 32;
        const float* p1 = p0 + 16;
        for (int i = 0; i < 16; i++) fused[n][i] = p0[i];
        for (int i = 0; i < 3; i++)
            for (int j = 0; j < 4; j++) {
                float s = 0.0f;
                for (int k = 0; k < 3; k++) s += p1[i*4+k] * p0[k*4+j];
                fused[n][i*4+j] = s;
            }
    }
    float a[4][8];
    for (int i = 0; i < 4; i++)
        for (int j = 0; j < 4; j++) {
            a[i][j]   = fused[0][i*4+j];
            a[i][j+4] = (i == j) ? 1.0f : 0.0f;
        }
    for (int col = 0; col < 4; col++) {
        int piv = col;
        for (int r = col + 1; r < 4; r++)
            if (fabsf(a[r][col]) > fabsf(a[piv][col])) piv = r;
        if (piv != col)
            for (int j = 0; j < 8; j++) { float t = a[col][j]; a[col][j] = a[piv][j]; a[piv][j] = t; }
        float d = a[col][col];
        for (int j = 0; j < 8; j++) a[col][j] /= d;
        for (int r = 0; r < 4; r++) {
            if (r == col) continue;
            float f = a[r][col];
            for (int j = 0; j < 8; j++) a[r][j] -= f * a[col][j];
        }
    }
    float inv[16];
    for (int i = 0; i < 4; i++)
        for (int j = 0; j < 4; j++) inv[i*4+j] = a[i][j+4];

    for (int v = 1; v < NV; v++) {
        float P[16];
        for (int i = 0; i < 4; i++)
            for (int j = 0; j < 4; j++) {
                float s = 0.0f;
                for (int k = 0; k < 4; k++) s += fused[v][i*4+k] * inv[k*4+j];
                P[i*4+j] = s;
            }
        for (int i = 0; i < 3; i++)
            for (int j = 0; j < 3; j++) g_rot[v-1][i*3+j] = P[i*4+j];
        for (int i = 0; i < 3; i++) g_trans[v-1][i] = P[i*4+3];
    }
}

// ---------------- kernel 1: transpose (N,C,H,W) fp32 -> (N,HW,C) fp16 -------
__global__ void k_transpose(const float* __restrict__ f) {
    __shared__ float tile[32][33];
    int n  = blockIdx.z;
    int p0 = blockIdx.x * 32;
    int tx = threadIdx.x, ty = threadIdx.y;
    tile[ty][tx] = f[((size_t)(n*CC + ty))*HWSZ + p0 + tx];
    __syncthreads();
    g_feaH[((size_t)(n*HWSZ + p0 + ty))*CC + tx] = __float2half(tile[tx][ty]);
}

// ---------------- kernel 2: warp + variance, HFMA2 interp + f32x2 accum -----
__global__ void __launch_bounds__(128) k_var(const float* __restrict__ dv) {
    __shared__ int4  s_idx[4][4][32];
    __shared__ uint4 s_wth[4][4][32];   // {w,w} half2 x4 per (point, view)
    __shared__ int   s_hw [4][32];
    __shared__ float s_var[128*33];

    const int tid  = threadIdx.x;
    const int warp = tid >> 5;
    const int lane = tid & 31;
    const int gblock = blockIdx.x * 128;

    // ---- phase 1: per-thread projection descriptors for one point ----
    {
        int g  = gblock + tid;
        int d  = g / HWSZ;
        int hw = g - d * HWSZ;
        int h  = hw / WW;
        int w  = hw - h * WW;
        float fx = (float)w, fy = (float)h;
        float depth = __ldg(dv + d);
        #pragma unroll
        for (int v = 0; v < NS; v++) {
            float r0 = g_rot[v][0], r1 = g_rot[v][1], r2 = g_rot[v][2];
            float r3 = g_rot[v][3], r4 = g_rot[v][4], r5 = g_rot[v][5];
            float r6 = g_rot[v][6], r7 = g_rot[v][7], r8 = g_rot[v][8];
            float t0 = g_trans[v][0], t1 = g_trans[v][1], t2 = g_trans[v][2];
            float rx = r0*fx + r1*fy + r2;
            float ry = r3*fx + r4*fy + r5;
            float rz = r6*fx + r7*fy + r8;
            float X = rx*depth + t0;
            float Y = ry*depth + t1;
            float Z = rz*depth + t2;
            float px = __fdividef(X, Z);
            float py = __fdividef(Y, Z);
            float x0 = floorf(px), y0 = floorf(py);
            float x1 = x0 + 1.0f,  y1 = y0 + 1.0f;
            float wx1 = px - x0, wx0 = 1.0f - wx1;
            float wy1 = py - y0, wy0 = 1.0f - wy1;
            bool vx0 = (x0 >= 0.0f) && (x0 <= (float)(WW-1));
            bool vx1 = (x1 >= 0.0f) && (x1 <= (float)(WW-1));
            bool vy0 = (y0 >= 0.0f) && (y0 <= (float)(HH-1));
            bool vy1 = (y1 >= 0.0f) && (y1 <= (float)(HH-1));
            int cx0 = (int)fminf(fmaxf(x0, 0.0f), (float)(WW-1));
            int cx1 = (int)fminf(fmaxf(x1, 0.0f), (float)(WW-1));
            int cy0 = (int)fminf(fmaxf(y0, 0.0f), (float)(HH-1));
            int cy1 = (int)fminf(fmaxf(y1, 0.0f), (float)(HH-1));
            int4 id;
            id.x = cy0*WW + cx0;
            id.y = cy0*WW + cx1;
            id.z = cy1*WW + cx0;
            id.w = cy1*WW + cx1;
            float w00 = wx0*wy0 * ((vx0 && vy0) ? 1.0f : 0.0f);
            float w01 = wx1*wy0 * ((vx1 && vy0) ? 1.0f : 0.0f);
            float w10 = wx0*wy1 * ((vx0 && vy1) ? 1.0f : 0.0f);
            float w11 = wx1*wy1 * ((vx1 && vy1) ? 1.0f : 0.0f);
            __half2 h0 = __float2half2_rn(w00);
            __half2 h1 = __float2half2_rn(w01);
            __half2 h2 = __float2half2_rn(w10);
            __half2 h3 = __float2half2_rn(w11);
            uint4 wh;
            wh.x = *reinterpret_cast<unsigned int*>(&h0);
            wh.y = *reinterpret_cast<unsigned int*>(&h1);
            wh.z = *reinterpret_cast<unsigned int*>(&h2);
            wh.w = *reinterpret_cast<unsigned int*>(&h3);
            s_idx[warp][v][lane] = id;
            s_wth[warp][v][lane] = wh;
        }
        s_hw[warp][lane] = hw;
    }
    __syncwarp();

    // ---- phase 2: lanes = (cg 0..3 x q 0..7); 8 channels per thread --------
    const int cg = lane & 3;          // uint4 = 8 fp16 channels
    const int q  = lane >> 2;
    const uint4* fH4 = (const uint4*)g_feaH;   // pixel stride = 4 uint4
    const float invN = 1.0f / (float)NV;

    #pragma unroll
    for (int it = 0; it < 4; it++) {
        int pt  = it*8 + q;
        int hw2 = s_hw[warp][pt];
        uint4 rf = fH4[(size_t)hw2*4 + cg];
        unsigned long long s0, s1, s2, s3;
        {
            float2 f;
            f = __half22float2(u2h(rf.x)); s0 = pk2(f.x, f.y);
            f = __half22float2(u2h(rf.y)); s1 = pk2(f.x, f.y);
            f = __half22float2(u2h(rf.z)); s2 = pk2(f.x, f.y);
            f = __half22float2(u2h(rf.w)); s3 = pk2(f.x, f.y);
        }
        unsigned long long q0 = mul2(s0, s0);
        unsigned long long q1 = mul2(s1, s1);
        unsigned long long q2 = mul2(s2, s2);
        unsigned long long q3 = mul2(s3, s3);
        #pragma unroll
        for (int v = 0; v < NS; v++) {
            int4  id = s_idx[warp][v][pt];
            uint4 wh = s_wth[warp][v][pt];
            const uint4* fv = fH4 + (size_t)(v+1)*HWSZ*4;
            uint4 c00 = fv[(size_t)id.x*4 + cg];
            uint4 c01 = fv[(size_t)id.y*4 + cg];
            uint4 c10 = fv[(size_t)id.z*4 + cg];
            uint4 c11 = fv[(size_t)id.w*4 + cg];
            unsigned long long v0 = interp_word(c00.x, c01.x, c10.x, c11.x, wh.x, wh.y, wh.z, wh.w);
            unsigned long long v1 = interp_word(c00.y, c01.y, c10.y, c11.y, wh.x, wh.y, wh.z, wh.w);
            unsigned long long v2 = interp_word(c00.z, c01.z, c10.z, c11.z, wh.x, wh.y, wh.z, wh.w);
            unsigned long long v3 = interp_word(c00.w, c01.w, c10.w, c11.w, wh.x, wh.y, wh.z, wh.w);
            s0 = add2(s0, v0); q0 = fma2(v0, v0, q0);
            s1 = add2(s1, v1); q1 = fma2(v1, v1, q1);
            s2 = add2(s2, v2); q2 = fma2(v2, v2, q2);
            s3 = add2(s3, v3); q3 = fma2(v3, v3, q3);
        }
        // finalize 8 channels
        float sa[8], qa[8];
        upk2(s0, sa[0], sa[1]); upk2(s1, sa[2], sa[3]);
        upk2(s2, sa[4], sa[5]); upk2(s3, sa[6], sa[7]);
        upk2(q0, qa[0], qa[1]); upk2(q1, qa[2], qa[3]);
        upk2(q2, qa[4], qa[5]); upk2(q3, qa[6], qa[7]);
        int sbase = (warp*32 + pt)*33 + cg*8;
        #pragma unroll
        for (int j = 0; j < 8; j++) {
            float m = sa[j] * invN;
            s_var[sbase + j] = qa[j]*invN - m*m;
        }
    }
    __syncthreads();

    // ---- planar write (fp16, pixel-pair packed): g_varH[c][gblock + 2p..] --
    {
        const int p  = (tid & 63) * 2;        // pixel pair within block
        const int cb = (tid >> 6) * 16;       // channel half
        const size_t gb = (size_t)gblock + p;
        #pragma unroll
        for (int j = 0; j < 16; j++) {
            int c = cb + j;
            __half2 hv = __floats2half2_rn(s_var[p*33 + c], s_var[(p+1)*33 + c]);
            *reinterpret_cast<unsigned int*>(g_varH + (size_t)c*DHWSZ + gb) =
                *reinterpret_cast<unsigned int*>(&hv);
        }
    }
}

// ---------------- kernel 3: 3x3x3 conv, fp16 slab, 5 blocks/SM --------------
__global__ void __launch_bounds__(CONV_THREADS, 5) k_conv(const float* __restrict__ wgt) {
    __shared__ __half slabH[HS][DS][WPH];           // 16.1 KB
    __shared__ unsigned long long wpk[CPB*27];

    const int tid = threadIdx.x;
    const int h0  = blockIdx.x * HT;
    const int d0  = blockIdx.y * DT;
    const int c0  = blockIdx.z * CPB;
    float* __restrict__ outbuf = g_costp[blockIdx.z];
    const int wg  = tid % 40;
    const int hl  = tid / 40;
    const int w0  = wg * 4;

    for (int i = tid; i < CPB*27; i += CONV_THREADS) {
        float k = __ldg(wgt + c0*27 + i);
        wpk[i] = pk2(k, k);
    }
    // zero halo: halves [0,2) and [162,168) of every row
    for (int i = tid; i < HS*DS; i += CONV_THREADS) {
        int shy = i / DS, sdd = i % DS;
        __half* row = &slabH[shy][sdd][0];
        *reinterpret_cast<unsigned int*>(row)       = 0u;          // halves 0,1
        *reinterpret_cast<unsigned int*>(row + 162) = 0u;          // 162,163
        *reinterpret_cast<unsigned int*>(row + 164) = 0u;          // 164,165
        *reinterpret_cast<unsigned int*>(row + 166) = 0u;          // 166,167
    }

    unsigned long long A[DT][2];
    #pragma unroll
    for (int od = 0; od < DT; od++) { A[od][0] = 0ull; A[od][1] = 0ull; }

    #pragma unroll 1
    for (int c = 0; c < CPB; c++) {
        __syncthreads();

        // ---- cooperative slab copy: 48 rows x 20 uint4 (8 halves) = 960 ----
        const __half* __restrict__ vc = g_varH + (size_t)(c0 + c) * DHWSZ;
        #pragma unroll
        for (int r = 0; r < 6; r++) {
            int idx = r*CONV_THREADS + tid;          // 0..959
            int row = idx / 20;                      // 0..47
            int w8  = (idx % 20) * 8;
            int shy = row / DS;                      // 0..5
            int sdd = row - shy*DS;                  // 0..7
            int dd  = d0 - 1 + sdd;
            int hy  = h0 - 1 + shy;
            uint4 v = make_uint4(0u, 0u, 0u, 0u);
            if (dd >= 0 && dd < DDEP && hy >= 0 && hy < HH)
                v = *(const uint4*)(vc + (size_t)dd*HWSZ + hy*WW + w8);
            unsigned int* dst = reinterpret_cast<unsigned int*>(&slabH[shy][sdd][2 + w8]);
            dst[0] = v.x; dst[1] = v.y; dst[2] = v.z; dst[3] = v.w;
        }
        __syncthreads();

        const unsigned long long* wc = wpk + c*27;
        #pragma unroll
        for (int dy = 0; dy < 3; dy++) {
            unsigned long long k00 = wc[(0*3+dy)*3+0], k01 = wc[(0*3+dy)*3+1], k02 = wc[(0*3+dy)*3+2];
            unsigned long long k10 = wc[(1*3+dy)*3+0], k11 = wc[(1*3+dy)*3+1], k12 = wc[(1*3+dy)*3+2];
            unsigned long long k20 = wc[(2*3+dy)*3+0], k21 = wc[(2*3+dy)*3+1], k22 = wc[(2*3+dy)*3+2];
            const __half* hrow = &slabH[hl + dy][0][0];
            #pragma unroll
            for (int sdd = 0; sdd < DS; sdd++) {
                const __half* col = hrow + sdd*WPH;
                // halves at index (2 + w0 + j) hold value v_j; reads 8B-aligned
                uint2 u0 = *(const uint2*)(col + w0);       // (v-2,v-1),(v0,v1)
                uint2 u1 = *(const uint2*)(col + w0 + 4);   // (v2,v3),(v4,v5)
                float2 fA = __half22float2(u2h(u0.x));
                float2 fB = __half22float2(u2h(u0.y));
                float2 fC = __half22float2(u2h(u1.x));
                float2 fD = __half22float2(u2h(u1.y));
                unsigned long long P0 = pk2(fA.y, fB.x);    // (v-1,v0)
                unsigned long long P1 = pk2(fB.x, fB.y);    // (v0,v1)
                unsigned long long P2 = pk2(fB.y, fC.x);    // (v1,v2)
                unsigned long long P3 = pk2(fC.x, fC.y);    // (v2,v3)
                unsigned long long P4 = pk2(fC.y, fD.x);    // (v3,v4)
                #pragma unroll
                for (int dz = 0; dz < 3; dz++) {
                    int od = sdd - dz;
                    if (od < 0 || od >= DT) continue;
                    unsigned long long q0 = (dz==0) ? k00 : (dz==1) ? k10 : k20;
                    unsigned long long q1 = (dz==0) ? k01 : (dz==1) ? k11 : k21;
                    unsigned long long q2 = (dz==0) ? k02 : (dz==1) ? k12 : k22;
                    A[od][0] = fma2(P0, q0, A[od][0]);
                    A[od][0] = fma2(P1, q1, A[od][0]);
                    A[od][0] = fma2(P2, q2, A[od][0]);
                    A[od][1] = fma2(P2, q0, A[od][1]);
                    A[od][1] = fma2(P3, q1, A[od][1]);
                    A[od][1] = fma2(P4, q2, A[od][1]);
                }
            }
        }
    }

    const int ob = (h0 + hl)*WW + w0;
    #pragma unroll
    for (int od = 0; od < DT; od++) {
        float o0, o1, o2, o3;
        upk2(A[od][0], o0, o1);
        upk2(A[od][1], o2, o3);
        float4 v = make_float4(o0, o1, o2, o3);
        *(float4*)(outbuf + (size_t)(d0 + od)*HWSZ + ob) = v;
    }
}

// ---------------- kernel 4: softmax / depth / confidence --------------------
__global__ void __launch_bounds__(128) k_post(const float* __restrict__ dv,
                                              float* __restrict__ out) {
    int pix = blockIdx.x * 128 + threadIdx.x;
    float p[DDEP];
    float mx = -1e30f;
    #pragma unroll
    for (int d = 0; d < DDEP; d++) {
        size_t o = (size_t)d*HWSZ + pix;
        p[d] = (g_costp[0][o] + g_costp[1][o]) + (g_costp[2][o] + g_costp[3][o]);
        mx = fmaxf(mx, p[d]);
    }
    float s = 0.0f;
    #pragma unroll
    for (int d = 0; d < DDEP; d++) { p[d] = expf(p[d] - mx); s += p[d]; }
    float inv = 1.0f / s;
    float depth = 0.0f, didx = 0.0f;
    #pragma unroll
    for (int d = 0; d < DDEP; d++) {
        float pr = p[d] * inv;
        p[d] = pr;
        depth += pr * __ldg(dv + d);
        didx  += pr * (float)d;
    }
    int di = (int)didx;
    di = min(max(di, 0), DDEP - 1);
    float conf = 0.0f;
    #pragma unroll
    for (int d = 0; d < DDEP; d++) {
        bool inwin = (d >= di - 1) && (d <= di + 2);
        conf += inwin ? p[d] : 0.0f;
    }
    out[pix]        = depth;
    out[HWSZ + pix] = conf;
}

// ---------------- launcher ---------------------------------------------------
extern "C" void kernel_launch(void* const* d_in, const int* in_sizes, int n_in,
                              void* d_out, int out_size) {
    const float* features = nullptr;
    const float* pm       = nullptr;
    const float* dv       = nullptr;
    const float* wgt      = nullptr;
    for (int i = 0; i < n_in; i++) {
        switch (in_sizes[i]) {
            case NV*CC*HWSZ: features = (const float*)d_in[i]; break;
            case 160:        pm       = (const float*)d_in[i]; break;
            case 48:         dv       = (const float*)d_in[i]; break;
            case 864:        wgt      = (const float*)d_in[i]; break;
            default: break;
        }
    }
    if (!features) features = (const float*)d_in[0];
    if (!pm)       pm       = (const float*)d_in[1];
    if (!dv)       dv       = (const float*)d_in[2];
    if (!wgt)      wgt      = (const float*)d_in[3];
    float* out = (float*)d_out;

    k_setup<<<1, 32>>>(pm);
    k_transpose<<<dim3(HWSZ/32, 1, NV), dim3(32, 32)>>>(features);
    k_var<<<DHWSZ/128, 128>>>(dv);
    k_conv<<<dim3(HH/HT, DDEP/DT, CSPLIT), CONV_THREADS>>>(wgt);
    k_post<<<HWSZ/128, 128>>>(dv, out);
}

// round 15
// speedup vs baseline: 1.3865x; 1.0533x over previous
#include <cuda_runtime.h>
#include <cuda_fp16.h>

#define NV 5
#define NS 4
#define CC 32
#define HH 128
#define WW 160
#define DDEP 48
#define HWSZ (HH*WW)          // 20480
#define DHWSZ (DDEP*HWSZ)     // 983040

// conv tiling
#define HT 4
#define HS 6
#define DT 6
#define DS 8
#define WPH 168               // halves per slab row: 2 halo + 160 + 6 pad
#define SLAB_HALVES (HS*DS*WPH)
#define CONV_THREADS 160
#define CSPLIT 4
#define CPB (CC/CSPLIT)       // 8 channels per block

// ---------------- scratch ----------------------------------------------------
__device__ float g_rot[NS][9];
__device__ float g_trans[NS][3];
__device__ __half g_feaH[NV*HWSZ*CC];           // (view, h, w, c) fp16, 6.5 MB
__device__ __half g_varH[(size_t)CC*DHWSZ];     // planar (c, d,h,w) fp16, 63 MB
__device__ float g_costp[CSPLIT][DHWSZ];        // partial costs

// ---------------- packed f32x2 helpers --------------------------------------
__device__ __forceinline__ unsigned long long pk2(float lo, float hi) {
    unsigned long long p;
    asm("mov.b64 %0, {%1, %2};" : "=l"(p) : "f"(lo), "f"(hi));
    return p;
}
__device__ __forceinline__ unsigned long long fma2(unsigned long long a,
                                                   unsigned long long b,
                                                   unsigned long long c) {
    unsigned long long d;
    asm("fma.rn.f32x2 %0, %1, %2, %3;" : "=l"(d) : "l"(a), "l"(b), "l"(c));
    return d;
}
__device__ __forceinline__ unsigned long long mul2(unsigned long long a,
                                                   unsigned long long b) {
    unsigned long long d;
    asm("mul.rn.f32x2 %0, %1, %2;" : "=l"(d) : "l"(a), "l"(b));
    return d;
}
__device__ __forceinline__ unsigned long long add2(unsigned long long a,
                                                   unsigned long long b) {
    unsigned long long d;
    asm("add.rn.f32x2 %0, %1, %2;" : "=l"(d) : "l"(a), "l"(b));
    return d;
}
__device__ __forceinline__ void upk2(unsigned long long p, float& lo, float& hi) {
    asm("mov.b64 {%0, %1}, %2;" : "=f"(lo), "=f"(hi) : "l"(p));
}
__device__ __forceinline__ __half2 u2h(unsigned int x) {
    return *reinterpret_cast<__half2*>(&x);
}
// fp16 bilinear for one half2 word; result as packed f32x2
__device__ __forceinline__ unsigned long long interp_word(
    unsigned int a00, unsigned int a01, unsigned int a10, unsigned int a11,
    unsigned int w0,  unsigned int w1,  unsigned int w2,  unsigned int w3)
{
    __half2 v = __hmul2(u2h(a11), u2h(w3));
    v = __hfma2(u2h(a10), u2h(w2), v);
    v = __hfma2(u2h(a01), u2h(w1), v);
    v = __hfma2(u2h(a00), u2h(w0), v);
    float2 f = __half22float2(v);
    return pk2(f.x, f.y);
}

// ---------------- kernel 0: projection setup (1 thread, fp32) ---------------
__global__ void k_setup(const float* __restrict__ pm) {
    if (threadIdx.x != 0 || blockIdx.x != 0) return;
    float fused[NV][16];
    for (int n = 0; n < NV; n++) {
        const float* p0 = pm + n * 32;
        const float* p1 = p0 + 16;
        for (int i = 0; i < 16; i++) fused[n][i] = p0[i];
        for (int i = 0; i < 3; i++)
            for (int j = 0; j < 4; j++) {
                float s = 0.0f;
                for (int k = 0; k < 3; k++) s += p1[i*4+k] * p0[k*4+j];
                fused[n][i*4+j] = s;
            }
    }
    float a[4][8];
    for (int i = 0; i < 4; i++)
        for (int j = 0; j < 4; j++) {
            a[i][j]   = fused[0][i*4+j];
            a[i][j+4] = (i == j) ? 1.0f : 0.0f;
        }
    for (int col = 0; col < 4; col++) {
        int piv = col;
        for (int r = col + 1; r < 4; r++)
            if (fabsf(a[r][col]) > fabsf(a[piv][col])) piv = r;
        if (piv != col)
            for (int j = 0; j < 8; j++) { float t = a[col][j]; a[col][j] = a[piv][j]; a[piv][j] = t; }
        float rd = 1.0f / a[col][col];
        for (int j = 0; j < 8; j++) a[col][j] *= rd;
        for (int r = 0; r < 4; r++) {
            if (r == col) continue;
            float f = a[r][col];
            for (int j = 0; j < 8; j++) a[r][j] -= f * a[col][j];
        }
    }
    float inv[16];
    for (int i = 0; i < 4; i++)
        for (int j = 0; j < 4; j++) inv[i*4+j] = a[i][j+4];

    for (int v = 1; v < NV; v++) {
        float P[16];
        for (int i = 0; i < 4; i++)
            for (int j = 0; j < 4; j++) {
                float s = 0.0f;
                for (int k = 0; k < 4; k++) s += fused[v][i*4+k] * inv[k*4+j];
                P[i*4+j] = s;
            }
        for (int i = 0; i < 3; i++)
            for (int j = 0; j < 3; j++) g_rot[v-1][i*3+j] = P[i*4+j];
        for (int i = 0; i < 3; i++) g_trans[v-1][i] = P[i*4+3];
    }
}

// ---------------- kernel 1: transpose (vectorized) --------------------------
// block: 1024 thr, tile = 32 channels x 128 pixels of one view
__global__ void __launch_bounds__(1024) k_transpose(const float* __restrict__ f) {
    __shared__ float tile[32][129];
    const int n   = blockIdx.y;
    const int p0  = blockIdx.x * 128;
    const int tid = threadIdx.x;

    // load: thread (c = tid>>5, xg = tid&31) reads float4 of 4 pixels
    {
        int c  = tid >> 5;
        int xg = tid & 31;
        float4 v = *(const float4*)(f + ((size_t)(n*CC + c))*HWSZ + p0 + xg*4);
        float* dst = &tile[c][xg*4];
        dst[0] = v.x; dst[1] = v.y; dst[2] = v.z; dst[3] = v.w;
    }
    __syncthreads();

    // store: thread (pix = tid>>3, cg = tid&7) writes 4 fp16 channels of 1 pixel
    {
        int pix = tid >> 3;
        int cg  = tid & 7;
        float a0 = tile[cg*4+0][pix];
        float a1 = tile[cg*4+1][pix];
        float a2 = tile[cg*4+2][pix];
        float a3 = tile[cg*4+3][pix];
        __half2 h0 = __floats2half2_rn(a0, a1);
        __half2 h1 = __floats2half2_rn(a2, a3);
        uint2 u;
        u.x = *reinterpret_cast<unsigned int*>(&h0);
        u.y = *reinterpret_cast<unsigned int*>(&h1);
        *reinterpret_cast<uint2*>(g_feaH + ((size_t)(n*HWSZ) + p0 + pix)*CC + cg*4) = u;
    }
}

// ---------------- kernel 2: warp + variance, HFMA2 interp + f32x2 accum -----
__global__ void __launch_bounds__(128) k_var(const float* __restrict__ dv) {
    __shared__ int4  s_idx[4][4][32];
    __shared__ uint4 s_wth[4][4][32];   // {w,w} half2 x4 per (point, view)
    __shared__ int   s_hw [4][32];
    __shared__ float s_var[128*33];

    const int tid  = threadIdx.x;
    const int warp = tid >> 5;
    const int lane = tid & 31;
    const int gblock = blockIdx.x * 128;

    // ---- phase 1: per-thread projection descriptors for one point ----
    {
        int g  = gblock + tid;
        int d  = g / HWSZ;
        int hw = g - d * HWSZ;
        int h  = hw / WW;
        int w  = hw - h * WW;
        float fx = (float)w, fy = (float)h;
        float depth = __ldg(dv + d);
        #pragma unroll
        for (int v = 0; v < NS; v++) {
            float r0 = g_rot[v][0], r1 = g_rot[v][1], r2 = g_rot[v][2];
            float r3 = g_rot[v][3], r4 = g_rot[v][4], r5 = g_rot[v][5];
            float r6 = g_rot[v][6], r7 = g_rot[v][7], r8 = g_rot[v][8];
            float t0 = g_trans[v][0], t1 = g_trans[v][1], t2 = g_trans[v][2];
            float rx = r0*fx + r1*fy + r2;
            float ry = r3*fx + r4*fy + r5;
            float rz = r6*fx + r7*fy + r8;
            float X = rx*depth + t0;
            float Y = ry*depth + t1;
            float Z = rz*depth + t2;
            float px = __fdividef(X, Z);
            float py = __fdividef(Y, Z);
            float x0 = floorf(px), y0 = floorf(py);
            float x1 = x0 + 1.0f,  y1 = y0 + 1.0f;
            float wx1 = px - x0, wx0 = 1.0f - wx1;
            float wy1 = py - y0, wy0 = 1.0f - wy1;
            bool vx0 = (x0 >= 0.0f) && (x0 <= (float)(WW-1));
            bool vx1 = (x1 >= 0.0f) && (x1 <= (float)(WW-1));
            bool vy0 = (y0 >= 0.0f) && (y0 <= (float)(HH-1));
            bool vy1 = (y1 >= 0.0f) && (y1 <= (float)(HH-1));
            int cx0 = (int)fminf(fmaxf(x0, 0.0f), (float)(WW-1));
            int cx1 = (int)fminf(fmaxf(x1, 0.0f), (float)(WW-1));
            int cy0 = (int)fminf(fmaxf(y0, 0.0f), (float)(HH-1));
            int cy1 = (int)fminf(fmaxf(y1, 0.0f), (float)(HH-1));
            int4 id;
            id.x = cy0*WW + cx0;
            id.y = cy0*WW + cx1;
            id.z = cy1*WW + cx0;
            id.w = cy1*WW + cx1;
            float w00 = wx0*wy0 * ((vx0 && vy0) ? 1.0f : 0.0f);
            float w01 = wx1*wy0 * ((vx1 && vy0) ? 1.0f : 0.0f);
            float w10 = wx0*wy1 * ((vx0 && vy1) ? 1.0f : 0.0f);
            float w11 = wx1*wy1 * ((vx1 && vy1) ? 1.0f : 0.0f);
            __half2 h0 = __float2half2_rn(w00);
            __half2 h1 = __float2half2_rn(w01);
            __half2 h2 = __float2half2_rn(w10);
            __half2 h3 = __float2half2_rn(w11);
            uint4 wh;
            wh.x = *reinterpret_cast<unsigned int*>(&h0);
            wh.y = *reinterpret_cast<unsigned int*>(&h1);
            wh.z = *reinterpret_cast<unsigned int*>(&h2);
            wh.w = *reinterpret_cast<unsigned int*>(&h3);
            s_idx[warp][v][lane] = id;
            s_wth[warp][v][lane] = wh;
        }
        s_hw[warp][lane] = hw;
    }
    __syncwarp();

    // ---- phase 2: lanes = (cg 0..3 x q 0..7); 8 channels per thread --------
    const int cg = lane & 3;          // uint4 = 8 fp16 channels
    const int q  = lane >> 2;
    const uint4* fH4 = (const uint4*)g_feaH;   // pixel stride = 4 uint4
    const float invN = 1.0f / (float)NV;

    #pragma unroll
    for (int it = 0; it < 4; it++) {
        int pt  = it*8 + q;
        int hw2 = s_hw[warp][pt];
        uint4 rf = fH4[(size_t)hw2*4 + cg];
        unsigned long long s0, s1, s2, s3;
        {
            float2 f;
            f = __half22float2(u2h(rf.x)); s0 = pk2(f.x, f.y);
            f = __half22float2(u2h(rf.y)); s1 = pk2(f.x, f.y);
            f = __half22float2(u2h(rf.z)); s2 = pk2(f.x, f.y);
            f = __half22float2(u2h(rf.w)); s3 = pk2(f.x, f.y);
        }
        unsigned long long q0 = mul2(s0, s0);
        unsigned long long q1 = mul2(s1, s1);
        unsigned long long q2 = mul2(s2, s2);
        unsigned long long q3 = mul2(s3, s3);
        #pragma unroll
        for (int v = 0; v < NS; v++) {
            int4  id = s_idx[warp][v][pt];
            uint4 wh = s_wth[warp][v][pt];
            const uint4* fv = fH4 + (size_t)(v+1)*HWSZ*4;
            uint4 c00 = fv[(size_t)id.x*4 + cg];
            uint4 c01 = fv[(size_t)id.y*4 + cg];
            uint4 c10 = fv[(size_t)id.z*4 + cg];
            uint4 c11 = fv[(size_t)id.w*4 + cg];
            unsigned long long v0 = interp_word(c00.x, c01.x, c10.x, c11.x, wh.x, wh.y, wh.z, wh.w);
            unsigned long long v1 = interp_word(c00.y, c01.y, c10.y, c11.y, wh.x, wh.y, wh.z, wh.w);
            unsigned long long v2 = interp_word(c00.z, c01.z, c10.z, c11.z, wh.x, wh.y, wh.z, wh.w);
            unsigned long long v3 = interp_word(c00.w, c01.w, c10.w, c11.w, wh.x, wh.y, wh.z, wh.w);
            s0 = add2(s0, v0); q0 = fma2(v0, v0, q0);
            s1 = add2(s1, v1); q1 = fma2(v1, v1, q1);
            s2 = add2(s2, v2); q2 = fma2(v2, v2, q2);
            s3 = add2(s3, v3); q3 = fma2(v3, v3, q3);
        }
        // finalize 8 channels
        float sa[8], qa[8];
        upk2(s0, sa[0], sa[1]); upk2(s1, sa[2], sa[3]);
        upk2(s2, sa[4], sa[5]); upk2(s3, sa[6], sa[7]);
        upk2(q0, qa[0], qa[1]); upk2(q1, qa[2], qa[3]);
        upk2(q2, qa[4], qa[5]); upk2(q3, qa[6], qa[7]);
        int sbase = (warp*32 + pt)*33 + cg*8;
        #pragma unroll
        for (int j = 0; j < 8; j++) {
            float m = sa[j] * invN;
            s_var[sbase + j] = qa[j]*invN - m*m;
        }
    }
    __syncthreads();

    // ---- planar write (fp16, pixel-pair packed): g_varH[c][gblock + 2p..] --
    {
        const int p  = (tid & 63) * 2;        // pixel pair within block
        const int cb = (tid >> 6) * 16;       // channel half
        const size_t gb = (size_t)gblock + p;
        #pragma unroll
        for (int j = 0; j < 16; j++) {
            int c = cb + j;
            __half2 hv = __floats2half2_rn(s_var[p*33 + c], s_var[(p+1)*33 + c]);
            *reinterpret_cast<unsigned int*>(g_varH + (size_t)c*DHWSZ + gb) =
                *reinterpret_cast<unsigned int*>(&hv);
        }
    }
}

// ---------------- kernel 3: 3x3x3 conv, double-buffered pipeline ------------
__global__ void __launch_bounds__(CONV_THREADS, 4) k_conv(const float* __restrict__ wgt) {
    __shared__ __half slabH[2][HS][DS][WPH];        // 32.3 KB
    __shared__ unsigned long long wpk[CPB*27];

    const int tid = threadIdx.x;
    const int h0  = blockIdx.x * HT;
    const int d0  = blockIdx.y * DT;
    const int c0  = blockIdx.z * CPB;
    float* __restrict__ outbuf = g_costp[blockIdx.z];
    const int wg  = tid % 40;
    const int hl  = tid / 40;
    const int w0  = wg * 4;

    for (int i = tid; i < CPB*27; i += CONV_THREADS) {
        float k = __ldg(wgt + c0*27 + i);
        wpk[i] = pk2(k, k);
    }
    // zero halos of BOTH buffers
    for (int i = tid; i < 2*HS*DS; i += CONV_THREADS) {
        int b   = i / (HS*DS);
        int rr  = i - b*(HS*DS);
        int shy = rr / DS, sdd = rr % DS;
        __half* row = &slabH[b][shy][sdd][0];
        *reinterpret_cast<unsigned int*>(row)       = 0u;
        *reinterpret_cast<unsigned int*>(row + 162) = 0u;
        *reinterpret_cast<unsigned int*>(row + 164) = 0u;
        *reinterpret_cast<unsigned int*>(row + 166) = 0u;
    }

    // ---- precompute per-thread copy descriptors (6 rows per thread) --------
    unsigned int srcOff[6], dstOff[6];
    bool vld[6];
    #pragma unroll
    for (int r = 0; r < 6; r++) {
        int idx = r*CONV_THREADS + tid;          // 0..959
        int row = idx / 20;                      // 0..47
        int w8  = (idx % 20) * 8;
        int shy = row / DS;                      // 0..5
        int sdd = row - shy*DS;                  // 0..7
        int dd  = d0 - 1 + sdd;
        int hy  = h0 - 1 + shy;
        vld[r] = (dd >= 0 && dd < DDEP && hy >= 0 && hy < HH);
        srcOff[r] = vld[r] ? (unsigned int)(dd*HWSZ + hy*WW + w8) : 0u;
        dstOff[r] = (unsigned int)((shy*DS + sdd)*WPH + 2 + w8);
    }
    __half* slabBase = &slabH[0][0][0][0];

    unsigned long long A[DT][2];
    #pragma unroll
    for (int od = 0; od < DT; od++) { A[od][0] = 0ull; A[od][1] = 0ull; }

    // ---- prologue: load channel 0 into buffer 0 ----
    {
        const __half* vc = g_varH + (size_t)c0 * DHWSZ;
        #pragma unroll
        for (int r = 0; r < 6; r++) {
            uint4 v = make_uint4(0u, 0u, 0u, 0u);
            if (vld[r]) v = *(const uint4*)(vc + srcOff[r]);
            unsigned int* dst = reinterpret_cast<unsigned int*>(slabBase + dstOff[r]);
            dst[0] = v.x; dst[1] = v.y; dst[2] = v.z; dst[3] = v.w;
        }
    }
    __syncthreads();

    const __half* vcn = g_varH + (size_t)(c0 + 1) * DHWSZ;
    #pragma unroll 1
    for (int c = 0; c < CPB; c++) {
        // prefetch next channel (LDGs issue before compute; latency hidden)
        uint4 ldn[6];
        const bool more = (c + 1 < CPB);
        if (more) {
            #pragma unroll
            for (int r = 0; r < 6; r++) {
                uint4 v = make_uint4(0u, 0u, 0u, 0u);
                if (vld[r]) v = *(const uint4*)(vcn + srcOff[r]);
                ldn[r] = v;
            }
        }

        // ---- compute from buffer c&1 ----
        const __half* slabCur = slabBase + (size_t)(c & 1) * SLAB_HALVES;
        const unsigned long long* wc = wpk + c*27;
        #pragma unroll
        for (int dy = 0; dy < 3; dy++) {
            unsigned long long k00 = wc[(0*3+dy)*3+0], k01 = wc[(0*3+dy)*3+1], k02 = wc[(0*3+dy)*3+2];
            unsigned long long k10 = wc[(1*3+dy)*3+0], k11 = wc[(1*3+dy)*3+1], k12 = wc[(1*3+dy)*3+2];
            unsigned long long k20 = wc[(2*3+dy)*3+0], k21 = wc[(2*3+dy)*3+1], k22 = wc[(2*3+dy)*3+2];
            const __half* hrow = slabCur + (size_t)(hl + dy)*DS*WPH;
            #pragma unroll
            for (int sdd = 0; sdd < DS; sdd++) {
                const __half* col = hrow + sdd*WPH;
                uint2 u0 = *(const uint2*)(col + w0);       // (v-2,v-1),(v0,v1)
                uint2 u1 = *(const uint2*)(col + w0 + 4);   // (v2,v3),(v4,v5)
                float2 fA = __half22float2(u2h(u0.x));
                float2 fB = __half22float2(u2h(u0.y));
                float2 fC = __half22float2(u2h(u1.x));
                float2 fD = __half22float2(u2h(u1.y));
                unsigned long long P0 = pk2(fA.y, fB.x);    // (v-1,v0)
                unsigned long long P1 = pk2(fB.x, fB.y);    // (v0,v1)
                unsigned long long P2 = pk2(fB.y, fC.x);    // (v1,v2)
                unsigned long long P3 = pk2(fC.x, fC.y);    // (v2,v3)
                unsigned long long P4 = pk2(fC.y, fD.x);    // (v3,v4)
                #pragma unroll
                for (int dz = 0; dz < 3; dz++) {
                    int od = sdd - dz;
                    if (od < 0 || od >= DT) continue;
                    unsigned long long q0 = (dz==0) ? k00 : (dz==1) ? k10 : k20;
                    unsigned long long q1 = (dz==0) ? k01 : (dz==1) ? k11 : k21;
                    unsigned long long q2 = (dz==0) ? k02 : (dz==1) ? k12 : k22;
                    A[od][0] = fma2(P0, q0, A[od][0]);
                    A[od][0] = fma2(P1, q1, A[od][0]);
                    A[od][0] = fma2(P2, q2, A[od][0]);
                    A[od][1] = fma2(P2, q0, A[od][1]);
                    A[od][1] = fma2(P3, q1, A[od][1]);
                    A[od][1] = fma2(P4, q2, A[od][1]);
                }
            }
        }

        // ---- store prefetched channel into the other buffer ----
        if (more) {
            __half* slabNxt = slabBase + (size_t)((c + 1) & 1) * SLAB_HALVES;
            #pragma unroll
            for (int r = 0; r < 6; r++) {
                unsigned int* dst = reinterpret_cast<unsigned int*>(slabNxt + dstOff[r]);
                dst[0] = ldn[r].x; dst[1] = ldn[r].y; dst[2] = ldn[r].z; dst[3] = ldn[r].w;
            }
            vcn += DHWSZ;
        }
        __syncthreads();
    }

    const int ob = (h0 + hl)*WW + w0;
    #pragma unroll
    for (int od = 0; od < DT; od++) {
        float o0, o1, o2, o3;
        upk2(A[od][0], o0, o1);
        upk2(A[od][1], o2, o3);
        float4 v = make_float4(o0, o1, o2, o3);
        *(float4*)(outbuf + (size_t)(d0 + od)*HWSZ + ob) = v;
    }
}

// ---------------- kernel 4: softmax / depth / confidence --------------------
__global__ void __launch_bounds__(128) k_post(const float* __restrict__ dv,
                                              float* __restrict__ out) {
    int pix = blockIdx.x * 128 + threadIdx.x;
    float p[DDEP];
    float mx = -1e30f;
    #pragma unroll
    for (int d = 0; d < DDEP; d++) {
        size_t o = (size_t)d*HWSZ + pix;
        p[d] = (g_costp[0][o] + g_costp[1][o]) + (g_costp[2][o] + g_costp[3][o]);
        mx = fmaxf(mx, p[d]);
    }
    float s = 0.0f;
    #pragma unroll
    for (int d = 0; d < DDEP; d++) { p[d] = expf(p[d] - mx); s += p[d]; }
    float inv = 1.0f / s;
    float depth = 0.0f, didx = 0.0f;
    #pragma unroll
    for (int d = 0; d < DDEP; d++) {
        float pr = p[d] * inv;
        p[d] = pr;
        depth += pr * __ldg(dv + d);
        didx  += pr * (float)d;
    }
    int di = (int)didx;
    di = min(max(di, 0), DDEP - 1);
    float conf = 0.0f;
    #pragma unroll
    for (int d = 0; d < DDEP; d++) {
        bool inwin = (d >= di - 1) && (d <= di + 2);
        conf += inwin ? p[d] : 0.0f;
    }
    out[pix]        = depth;
    out[HWSZ + pix] = conf;
}

// ---------------- launcher ---------------------------------------------------
extern "C" void kernel_launch(void* const* d_in, const int* in_sizes, int n_in,
                              void* d_out, int out_size) {
    const float* features = nullptr;
    const float* pm       = nullptr;
    const float* dv       = nullptr;
    const float* wgt      = nullptr;
    for (int i = 0; i < n_in; i++) {
        switch (in_sizes[i]) {
            case NV*CC*HWSZ: features = (const float*)d_in[i]; break;
            case 160:        pm       = (const float*)d_in[i]; break;
            case 48:         dv       = (const float*)d_in[i]; break;
            case 864:        wgt      = (const float*)d_in[i]; break;
            default: break;
        }
    }
    if (!features) features = (const float*)d_in[0];
    if (!pm)       pm       = (const float*)d_in[1];
    if (!dv)       dv       = (const float*)d_in[2];
    if (!wgt)      wgt      = (const float*)d_in[3];
    float* out = (float*)d_out;

    k_setup<<<1, 32>>>(pm);
    k_transpose<<<dim3(HWSZ/128, NV), 1024>>>(features);
    k_var<<<DHWSZ/128, 128>>>(dv);
    k_conv<<<dim3(HH/HT, DDEP/DT, CSPLIT), CONV_THREADS>>>(wgt);
    k_post<<<HWSZ/128, 128>>>(dv, out);
}